// round 1
// baseline (speedup 1.0000x reference)
#include <cuda_runtime.h>
#include <math.h>

#define SEQ 2048
#define DIM 512

// Scratch (no cudaMalloc allowed)
__device__ float g_xn  [SEQ * DIM];        // layernorm output
__device__ float g_qkv [SEQ * 3 * DIM];    // qkv projections
__device__ float g_attn[SEQ * DIM];        // attention output (pre out-proj)
__device__ float g_out [SEQ * DIM];        // residual + attn@w_out
__device__ float g_ffn1[SEQ * 4 * DIM];    // gelu(out@w1)

// ---------------------------------------------------------------------------
// LayerNorm: one block per row of 512, 256 threads x 2 elements
// ---------------------------------------------------------------------------
__global__ void __launch_bounds__(256) ln_kernel(
    const float* __restrict__ x, const float* __restrict__ g,
    const float* __restrict__ b, float* __restrict__ y)
{
    int s = blockIdx.x;
    int tid = threadIdx.x;
    const float* xr = x + (size_t)s * DIM;
    float v0 = xr[tid], v1 = xr[tid + 256];
    float sum = v0 + v1;
    float sq  = v0 * v0 + v1 * v1;
    #pragma unroll
    for (int o = 16; o > 0; o >>= 1) {
        sum += __shfl_xor_sync(0xFFFFFFFFu, sum, o);
        sq  += __shfl_xor_sync(0xFFFFFFFFu, sq,  o);
    }
    __shared__ float ss[8], s2[8];
    int w = tid >> 5, l = tid & 31;
    if (l == 0) { ss[w] = sum; s2[w] = sq; }
    __syncthreads();
    float tot = 0.f, tot2 = 0.f;
    #pragma unroll
    for (int i = 0; i < 8; i++) { tot += ss[i]; tot2 += s2[i]; }
    float mu  = tot * (1.0f / 512.0f);
    float var = tot2 * (1.0f / 512.0f) - mu * mu;
    float inv = rsqrtf(var + 1e-5f);
    float* yr = y + (size_t)s * DIM;
    yr[tid]       = (v0 - mu) * inv * g[tid]       + b[tid];
    yr[tid + 256] = (v1 - mu) * inv * g[tid + 256] + b[tid + 256];
}

// ---------------------------------------------------------------------------
// fp32 tiled GEMM: C[M,N] = A[M,K] @ B[K,N] (+bias, +residual / gelu)
// 64x64 block tile, BK=16, 256 threads, 4x4 register tile per thread.
// All dims are exact multiples of tile sizes for this problem -> no guards.
// EPI: 0 = +bias ; 1 = +bias +res ; 2 = gelu(+bias)
// ---------------------------------------------------------------------------
template<int EPI>
__global__ void __launch_bounds__(256) gemm_kernel(
    const float* __restrict__ A, const float* __restrict__ B,
    const float* __restrict__ bias, const float* __restrict__ res,
    float* __restrict__ C, int M, int N, int K)
{
    __shared__ float As[16][68];   // A tile stored transposed: As[k][m]
    __shared__ float Bs[16][68];   // Bs[k][n]

    int tid = threadIdx.x;
    int bm = blockIdx.y * 64;
    int bn = blockIdx.x * 64;

    int tx = tid & 15;        // 0..15  -> 4 cols
    int ty = tid >> 4;        // 0..15  -> 4 rows

    int ar = tid >> 2;            // 0..63 row of A tile
    int ac = (tid & 3) << 2;      // 0/4/8/12 col of A tile (float4)
    int br = tid >> 4;            // 0..15 row of B tile
    int bc = (tid & 15) << 2;     // 0..60 col of B tile (float4)

    float acc[4][4] = {};

    for (int k0 = 0; k0 < K; k0 += 16) {
        float4 av = *(const float4*)&A[(size_t)(bm + ar) * K + k0 + ac];
        float4 bv = *(const float4*)&B[(size_t)(k0 + br) * N + bn + bc];

        As[ac + 0][ar] = av.x;
        As[ac + 1][ar] = av.y;
        As[ac + 2][ar] = av.z;
        As[ac + 3][ar] = av.w;
        *(float4*)&Bs[br][bc] = bv;
        __syncthreads();

        #pragma unroll
        for (int kk = 0; kk < 16; kk++) {
            float4 a = *(const float4*)&As[kk][ty << 2];
            float4 b = *(const float4*)&Bs[kk][tx << 2];
            float ax[4] = {a.x, a.y, a.z, a.w};
            float bx[4] = {b.x, b.y, b.z, b.w};
            #pragma unroll
            for (int i = 0; i < 4; i++)
                #pragma unroll
                for (int j = 0; j < 4; j++)
                    acc[i][j] = fmaf(ax[i], bx[j], acc[i][j]);
        }
        __syncthreads();
    }

    int row0 = bm + (ty << 2);
    int col0 = bn + (tx << 2);
    #pragma unroll
    for (int i = 0; i < 4; i++) {
        float4 o;
        float* op = &o.x;
        #pragma unroll
        for (int j = 0; j < 4; j++) {
            float v = acc[i][j] + bias[col0 + j];
            if (EPI == 1) v += res[(size_t)(row0 + i) * N + col0 + j];
            if (EPI == 2) v = 0.5f * v * (1.0f + erff(v * 0.70710678118654752f));
            op[j] = v;
        }
        *(float4*)&C[(size_t)(row0 + i) * N + col0] = o;
    }
}

// ---------------------------------------------------------------------------
// Local windowed attention, window=128 -> W=129, ZERO-padded (not masked):
// out-of-range positions contribute score 0 to the softmax and v=0.
// One block per query position s; one warp per head.
// ---------------------------------------------------------------------------
__global__ void __launch_bounds__(256) local_attn_kernel(
    const float* __restrict__ qkv, float* __restrict__ attn_out)
{
    int s   = blockIdx.x;
    int tid = threadIdx.x;
    int h   = tid >> 5;       // warp = head
    int lane = tid & 31;

    __shared__ float qs[512];
    __shared__ float sc[8][132];

    for (int i = tid; i < 512; i += 256)
        qs[i] = qkv[(size_t)s * 1536 + i];
    __syncthreads();

    const float4* qh = (const float4*)&qs[h * 64];

    // scores: each lane owns positions j = lane, lane+32, ... (<= 129)
    for (int j = lane; j < 129; j += 32) {
        int t = s - 64 + j;
        float dot = 0.0f;
        if (t >= 0 && t < SEQ) {
            const float4* kp = (const float4*)&qkv[(size_t)t * 1536 + 512 + h * 64];
            #pragma unroll
            for (int d = 0; d < 16; d++) {
                float4 kv = kp[d];
                float4 qv = qh[d];
                dot += qv.x * kv.x + qv.y * kv.y + qv.z * kv.z + qv.w * kv.w;
            }
            dot *= 0.125f;   // 1/sqrt(64)
        }
        sc[h][j] = dot;      // OOB -> exactly 0, matches zero-pad reference
    }
    __syncwarp();

    // softmax over 129 entries (max-sub for stability)
    float m = -1e30f;
    for (int j = lane; j < 129; j += 32) m = fmaxf(m, sc[h][j]);
    #pragma unroll
    for (int o = 16; o > 0; o >>= 1) m = fmaxf(m, __shfl_xor_sync(0xFFFFFFFFu, m, o));

    float sum = 0.0f;
    for (int j = lane; j < 129; j += 32) {
        float e = __expf(sc[h][j] - m);
        sc[h][j] = e;
        sum += e;
    }
    #pragma unroll
    for (int o = 16; o > 0; o >>= 1) sum += __shfl_xor_sync(0xFFFFFFFFu, sum, o);
    float inv = 1.0f / sum;
    __syncwarp();

    // weighted sum of v: lane owns dims lane and lane+32
    float o0 = 0.0f, o1 = 0.0f;
    int jlo = (s - 64 < 0)        ? (64 - s)        : 0;
    int jhi = (s + 64 >= SEQ)     ? (SEQ - s + 64)  : 129;
    for (int j = jlo; j < jhi; j++) {
        int t = s - 64 + j;
        float p = sc[h][j];
        const float* vp = &qkv[(size_t)t * 1536 + 1024 + h * 64];
        o0 = fmaf(p, vp[lane],      o0);
        o1 = fmaf(p, vp[lane + 32], o1);
    }
    attn_out[(size_t)s * DIM + h * 64 + lane]      = o0 * inv;
    attn_out[(size_t)s * DIM + h * 64 + lane + 32] = o1 * inv;
}

// ---------------------------------------------------------------------------
extern "C" void kernel_launch(void* const* d_in, const int* in_sizes, int n_in,
                              void* d_out, int out_size)
{
    const float* x     = (const float*)d_in[0];
    const float* w_qkv = (const float*)d_in[1];
    const float* b_qkv = (const float*)d_in[2];
    const float* w_out = (const float*)d_in[3];
    const float* b_out = (const float*)d_in[4];
    const float* ln_g  = (const float*)d_in[5];
    const float* ln_b  = (const float*)d_in[6];
    const float* w1    = (const float*)d_in[7];
    const float* b1    = (const float*)d_in[8];
    const float* w2    = (const float*)d_in[9];
    const float* b2    = (const float*)d_in[10];
    float* out = (float*)d_out;

    float *xn, *qkv, *attn, *o, *f1;
    cudaGetSymbolAddress((void**)&xn,   g_xn);
    cudaGetSymbolAddress((void**)&qkv,  g_qkv);
    cudaGetSymbolAddress((void**)&attn, g_attn);
    cudaGetSymbolAddress((void**)&o,    g_out);
    cudaGetSymbolAddress((void**)&f1,   g_ffn1);

    // 1) LayerNorm
    ln_kernel<<<SEQ, 256>>>(x, ln_g, ln_b, xn);
    // 2) QKV projection: [2048,512] @ [512,1536]
    gemm_kernel<0><<<dim3(1536 / 64, SEQ / 64), 256>>>(xn, w_qkv, b_qkv, nullptr, qkv, SEQ, 1536, 512);
    // 3) Local attention
    local_attn_kernel<<<SEQ, 256>>>(qkv, attn);
    // 4) Out projection + residual(x): [2048,512] @ [512,512]
    gemm_kernel<1><<<dim3(512 / 64, SEQ / 64), 256>>>(attn, w_out, b_out, x, o, SEQ, 512, 512);
    // 5) FFN up + exact GELU: [2048,512] @ [512,2048]
    gemm_kernel<2><<<dim3(2048 / 64, SEQ / 64), 256>>>(o, w1, b1, nullptr, f1, SEQ, 2048, 512);
    // 6) FFN down + residual(out): [2048,2048] @ [2048,512]
    gemm_kernel<1><<<dim3(512 / 64, SEQ / 64), 256>>>(f1, w2, b2, o, out, SEQ, 512, 2048);
}

// round 3
// speedup vs baseline: 2.3066x; 2.3066x over previous
#include <cuda_runtime.h>
#include <cuda_fp16.h>
#include <math.h>
#include <cstdint>

#define SEQ 2048
#define DIM 512

// ---------------------------------------------------------------------------
// Scratch (no cudaMalloc allowed)
// ---------------------------------------------------------------------------
__device__ __align__(16) __half g_xn_h  [SEQ * DIM];
__device__ __align__(16) __half g_wqkv_t[1536 * 512];
__device__ __align__(16) __half g_wout_t[512 * 512];
__device__ __align__(16) __half g_w1_t  [2048 * 512];
__device__ __align__(16) __half g_w2_t  [512 * 2048];
__device__ __align__(16) __half g_qkv_h [SEQ * 1536];
__device__ __align__(16) __half g_attn_h[SEQ * DIM];
__device__ __align__(16) float  g_out_f [SEQ * DIM];
__device__ __align__(16) __half g_out_h [SEQ * DIM];
__device__ __align__(16) __half g_f1_h  [SEQ * 2048];

// ---------------------------------------------------------------------------
// PTX helpers (base sm_103 target: mma.sync + ldmatrix + cp.async only)
// ---------------------------------------------------------------------------
__device__ __forceinline__ uint32_t smem_u32(const void* p) {
    uint32_t a;
    asm("{ .reg .u64 t; cvta.to.shared.u64 t, %1; cvt.u32.u64 %0, t; }"
        : "=r"(a) : "l"(p));
    return a;
}
#define CP_ASYNC16(dst, src) \
    asm volatile("cp.async.cg.shared.global [%0], [%1], 16;" :: "r"(dst), "l"(src))
#define CP_COMMIT()  asm volatile("cp.async.commit_group;" ::: "memory")
#define CP_WAIT0()   asm volatile("cp.async.wait_group 0;" ::: "memory")

__device__ __forceinline__ void ldsm_x4(uint32_t& r0, uint32_t& r1,
                                        uint32_t& r2, uint32_t& r3, uint32_t a) {
    asm volatile("ldmatrix.sync.aligned.m8n8.x4.shared.b16 {%0,%1,%2,%3}, [%4];"
        : "=r"(r0), "=r"(r1), "=r"(r2), "=r"(r3) : "r"(a));
}
__device__ __forceinline__ void ldsm_x2(uint32_t& r0, uint32_t& r1, uint32_t a) {
    asm volatile("ldmatrix.sync.aligned.m8n8.x2.shared.b16 {%0,%1}, [%2];"
        : "=r"(r0), "=r"(r1) : "r"(a));
}
__device__ __forceinline__ void mma16816(float* c, const uint32_t* a, const uint32_t* b) {
    asm volatile("mma.sync.aligned.m16n8k16.row.col.f32.f16.f16.f32 "
        "{%0,%1,%2,%3}, {%4,%5,%6,%7}, {%8,%9}, {%0,%1,%2,%3};"
        : "+f"(c[0]), "+f"(c[1]), "+f"(c[2]), "+f"(c[3])
        : "r"(a[0]), "r"(a[1]), "r"(a[2]), "r"(a[3]), "r"(b[0]), "r"(b[1]));
}

// ---------------------------------------------------------------------------
// LayerNorm -> half
// ---------------------------------------------------------------------------
__global__ void __launch_bounds__(256) ln_kernel(
    const float* __restrict__ x, const float* __restrict__ g,
    const float* __restrict__ b, __half* __restrict__ y)
{
    int s = blockIdx.x, tid = threadIdx.x;
    const float* xr = x + (size_t)s * DIM;
    float v0 = xr[tid], v1 = xr[tid + 256];
    float sum = v0 + v1, sq = v0 * v0 + v1 * v1;
    #pragma unroll
    for (int o = 16; o > 0; o >>= 1) {
        sum += __shfl_xor_sync(~0u, sum, o);
        sq  += __shfl_xor_sync(~0u, sq,  o);
    }
    __shared__ float ss[8], s2[8];
    int w = tid >> 5, l = tid & 31;
    if (l == 0) { ss[w] = sum; s2[w] = sq; }
    __syncthreads();
    float tot = 0.f, tot2 = 0.f;
    #pragma unroll
    for (int i = 0; i < 8; i++) { tot += ss[i]; tot2 += s2[i]; }
    float mu = tot * (1.0f / 512.0f);
    float inv = rsqrtf(tot2 * (1.0f / 512.0f) - mu * mu + 1e-5f);
    __half* yr = y + (size_t)s * DIM;
    yr[tid]       = __float2half((v0 - mu) * inv * g[tid]       + b[tid]);
    yr[tid + 256] = __float2half((v1 - mu) * inv * g[tid + 256] + b[tid + 256]);
}

// ---------------------------------------------------------------------------
// Transpose + fp32->half:  in[K,N] fp32  ->  out[N,K] half
// ---------------------------------------------------------------------------
__global__ void __launch_bounds__(256) transpose_h_kernel(
    const float* __restrict__ in, __half* __restrict__ out, int K, int N)
{
    __shared__ float t[32][33];
    int k0 = blockIdx.y * 32, n0 = blockIdx.x * 32;
    int tx = threadIdx.x & 31, ty = threadIdx.x >> 5;
    #pragma unroll
    for (int i = ty; i < 32; i += 8)
        t[i][tx] = in[(size_t)(k0 + i) * N + n0 + tx];
    __syncthreads();
    #pragma unroll
    for (int i = ty; i < 32; i += 8)
        out[(size_t)(n0 + i) * K + k0 + tx] = __float2half(t[tx][i]);
}

// ---------------------------------------------------------------------------
// HMMA GEMM: C[M,N] = A_h[M,K] @ Bt_h[N,K]^T, fp32 accum.
// 128x128 CTA tile, BK=32, 8 warps (2x4), 64x32 per warp, cp.async dbl-buf.
// SMEM rows padded to 40 halfs (80B) -> conflict-free ldmatrix.
// EPI: 0 = +bias ; 1 = +bias +res ; 2 = gelu(+bias)
// ---------------------------------------------------------------------------
#define BK 32
#define SSTR 40   // halfs per smem row (32 data + 8 pad)

template<int EPI, bool WF32, bool WH>
__global__ void __launch_bounds__(256) gemm_mma(
    const __half* __restrict__ A, const __half* __restrict__ Bt,
    const float* __restrict__ bias, const float* __restrict__ res,
    float* __restrict__ C, __half* __restrict__ Ch,
    int M, int N, int K)
{
    __shared__ __half As[2][128 * SSTR];
    __shared__ __half Bs[2][128 * SSTR];

    int tid = threadIdx.x, wid = tid >> 5, lane = tid & 31;
    int bm = blockIdx.y * 128, bn = blockIdx.x * 128;
    int wm = wid >> 2, wn = wid & 3;          // warp 2x4 grid

    uint32_t asb = smem_u32(As), bsb = smem_u32(Bs);
    const uint32_t SSZ = 128 * SSTR * 2;      // bytes per stage

    // global->smem: 512 x 16B chunks per operand per stage, 2 per thread
    int ldr0 = (tid * 2) >> 2,      ldc0 = (tid * 2) & 3;
    int ldr1 = (tid * 2 + 1) >> 2,  ldc1 = (tid * 2 + 1) & 3;

    auto load_stage = [&](int kt, int s) {
        const __half* ag = A  + (size_t)(bm + ldr0) * K + kt * BK + ldc0 * 8;
        const __half* ag1= A  + (size_t)(bm + ldr1) * K + kt * BK + ldc1 * 8;
        const __half* bg = Bt + (size_t)(bn + ldr0) * K + kt * BK + ldc0 * 8;
        const __half* bg1= Bt + (size_t)(bn + ldr1) * K + kt * BK + ldc1 * 8;
        CP_ASYNC16(asb + s * SSZ + (ldr0 * SSTR + ldc0 * 8) * 2, ag);
        CP_ASYNC16(asb + s * SSZ + (ldr1 * SSTR + ldc1 * 8) * 2, ag1);
        CP_ASYNC16(bsb + s * SSZ + (ldr0 * SSTR + ldc0 * 8) * 2, bg);
        CP_ASYNC16(bsb + s * SSZ + (ldr1 * SSTR + ldc1 * 8) * 2, bg1);
    };

    float acc[4][4][4] = {};

    const int nK = K / BK;
    load_stage(0, 0);
    CP_COMMIT();
    CP_WAIT0();
    __syncthreads();

    int ar = lane & 15, ac = (lane >> 4) << 3;          // A ldmatrix addr comps
    int brr = lane & 7, bcc = ((lane >> 3) & 1) << 3;   // B ldmatrix addr comps

    for (int ks = 0; ks < nK; ks++) {
        int s = ks & 1;
        if (ks + 1 < nK) { load_stage(ks + 1, s ^ 1); CP_COMMIT(); }

        #pragma unroll
        for (int kk = 0; kk < BK; kk += 16) {
            uint32_t af[4][4], bf[4][2];
            #pragma unroll
            for (int i = 0; i < 4; i++) {
                uint32_t addr = asb + s * SSZ +
                    ((wm * 64 + i * 16 + ar) * SSTR + kk + ac) * 2;
                ldsm_x4(af[i][0], af[i][1], af[i][2], af[i][3], addr);
            }
            #pragma unroll
            for (int j = 0; j < 4; j++) {
                uint32_t addr = bsb + s * SSZ +
                    ((wn * 32 + j * 8 + brr) * SSTR + kk + bcc) * 2;
                ldsm_x2(bf[j][0], bf[j][1], addr);
            }
            #pragma unroll
            for (int i = 0; i < 4; i++)
                #pragma unroll
                for (int j = 0; j < 4; j++)
                    mma16816(acc[i][j], af[i], bf[j]);
        }

        if (ks + 1 < nK) CP_WAIT0();
        __syncthreads();
    }

    // Epilogue: thread t holds (m = q, q+8 ; n = 2r, 2r+1) per 16x8 tile
    int tq = lane >> 2, tr = lane & 3;
    #pragma unroll
    for (int i = 0; i < 4; i++) {
        int row = bm + wm * 64 + i * 16 + tq;
        #pragma unroll
        for (int j = 0; j < 4; j++) {
            int col = bn + wn * 32 + j * 8 + tr * 2;
            float b0 = bias[col], b1 = bias[col + 1];
            float v0 = acc[i][j][0] + b0, v1 = acc[i][j][1] + b1;
            float v2 = acc[i][j][2] + b0, v3 = acc[i][j][3] + b1;
            size_t p0 = (size_t)row * N + col;
            size_t p1 = (size_t)(row + 8) * N + col;
            if (EPI == 1) {
                float2 r0 = *(const float2*)&res[p0];
                float2 r1 = *(const float2*)&res[p1];
                v0 += r0.x; v1 += r0.y; v2 += r1.x; v3 += r1.y;
            }
            if (EPI == 2) {
                v0 = 0.5f * v0 * (1.0f + erff(v0 * 0.70710678118654752f));
                v1 = 0.5f * v1 * (1.0f + erff(v1 * 0.70710678118654752f));
                v2 = 0.5f * v2 * (1.0f + erff(v2 * 0.70710678118654752f));
                v3 = 0.5f * v3 * (1.0f + erff(v3 * 0.70710678118654752f));
            }
            if (WF32) {
                *(float2*)&C[p0] = make_float2(v0, v1);
                *(float2*)&C[p1] = make_float2(v2, v3);
            }
            if (WH) {
                *(__half2*)&Ch[p0] = __floats2half2_rn(v0, v1);
                *(__half2*)&Ch[p1] = __floats2half2_rn(v2, v3);
            }
        }
    }
}

// ---------------------------------------------------------------------------
// Local attention (W=129, ZERO-padded softmax). half in/out, fp32 math.
// ---------------------------------------------------------------------------
__global__ void __launch_bounds__(256) local_attn_kernel(
    const __half* __restrict__ qkv, __half* __restrict__ attn_out)
{
    int s = blockIdx.x, tid = threadIdx.x;
    int h = tid >> 5, lane = tid & 31;

    __shared__ float qs[512];
    __shared__ float sc[8][132];

    for (int i = tid; i < 512; i += 256)
        qs[i] = __half2float(qkv[(size_t)s * 1536 + i]);
    __syncthreads();

    const float* qh = &qs[h * 64];

    for (int j = lane; j < 129; j += 32) {
        int t = s - 64 + j;
        float dot = 0.0f;
        if (t >= 0 && t < SEQ) {
            const uint4* kp = (const uint4*)&qkv[(size_t)t * 1536 + 512 + h * 64];
            #pragma unroll
            for (int d = 0; d < 8; d++) {
                uint4 kv = kp[d];
                const __half2* h2 = (const __half2*)&kv;
                const float* qv = &qh[d * 8];
                #pragma unroll
                for (int e = 0; e < 4; e++) {
                    float2 f = __half22float2(h2[e]);
                    dot += qv[e * 2] * f.x + qv[e * 2 + 1] * f.y;
                }
            }
            dot *= 0.125f;
        }
        sc[h][j] = dot;   // OOB -> exactly 0 (zero-pad reference)
    }
    __syncwarp();

    float m = -1e30f;
    for (int j = lane; j < 129; j += 32) m = fmaxf(m, sc[h][j]);
    #pragma unroll
    for (int o = 16; o > 0; o >>= 1) m = fmaxf(m, __shfl_xor_sync(~0u, m, o));

    float sum = 0.0f;
    for (int j = lane; j < 129; j += 32) {
        float e = __expf(sc[h][j] - m);
        sc[h][j] = e;
        sum += e;
    }
    #pragma unroll
    for (int o = 16; o > 0; o >>= 1) sum += __shfl_xor_sync(~0u, sum, o);
    float inv = 1.0f / sum;
    __syncwarp();

    float o0 = 0.0f, o1 = 0.0f;
    int jlo = (s - 64 < 0)    ? (64 - s)       : 0;
    int jhi = (s + 64 >= SEQ) ? (SEQ - s + 64) : 129;
    for (int j = jlo; j < jhi; j++) {
        int t = s - 64 + j;
        float p = sc[h][j];
        const __half* vp = &qkv[(size_t)t * 1536 + 1024 + h * 64];
        o0 = fmaf(p, __half2float(vp[lane]),      o0);
        o1 = fmaf(p, __half2float(vp[lane + 32]), o1);
    }
    attn_out[(size_t)s * DIM + h * 64 + lane]      = __float2half(o0 * inv);
    attn_out[(size_t)s * DIM + h * 64 + lane + 32] = __float2half(o1 * inv);
}

// ---------------------------------------------------------------------------
extern "C" void kernel_launch(void* const* d_in, const int* in_sizes, int n_in,
                              void* d_out, int out_size)
{
    const float* x     = (const float*)d_in[0];
    const float* w_qkv = (const float*)d_in[1];
    const float* b_qkv = (const float*)d_in[2];
    const float* w_out = (const float*)d_in[3];
    const float* b_out = (const float*)d_in[4];
    const float* ln_g  = (const float*)d_in[5];
    const float* ln_b  = (const float*)d_in[6];
    const float* w1    = (const float*)d_in[7];
    const float* b1    = (const float*)d_in[8];
    const float* w2    = (const float*)d_in[9];
    const float* b2    = (const float*)d_in[10];
    float* out = (float*)d_out;

    __half *xn, *wqkv_t, *wout_t, *w1_t, *w2_t, *qkv, *attn, *o_h, *f1;
    float *o_f;
    cudaGetSymbolAddress((void**)&xn,     g_xn_h);
    cudaGetSymbolAddress((void**)&wqkv_t, g_wqkv_t);
    cudaGetSymbolAddress((void**)&wout_t, g_wout_t);
    cudaGetSymbolAddress((void**)&w1_t,   g_w1_t);
    cudaGetSymbolAddress((void**)&w2_t,   g_w2_t);
    cudaGetSymbolAddress((void**)&qkv,    g_qkv_h);
    cudaGetSymbolAddress((void**)&attn,   g_attn_h);
    cudaGetSymbolAddress((void**)&o_f,    g_out_f);
    cudaGetSymbolAddress((void**)&o_h,    g_out_h);
    cudaGetSymbolAddress((void**)&f1,     g_f1_h);

    // Weight prep
    transpose_h_kernel<<<dim3(1536/32, 512/32),  256>>>(w_qkv, wqkv_t, 512, 1536);
    transpose_h_kernel<<<dim3(512/32,  512/32),  256>>>(w_out, wout_t, 512, 512);
    transpose_h_kernel<<<dim3(2048/32, 512/32),  256>>>(w1,    w1_t,   512, 2048);
    transpose_h_kernel<<<dim3(512/32,  2048/32), 256>>>(w2,    w2_t,   2048, 512);

    // 1) LayerNorm -> half
    ln_kernel<<<SEQ, 256>>>(x, ln_g, ln_b, xn);
    // 2) QKV: [2048,512] @ [512,1536]^T-form -> half
    gemm_mma<0, false, true><<<dim3(1536/128, SEQ/128), 256>>>(
        xn, wqkv_t, b_qkv, nullptr, nullptr, qkv, SEQ, 1536, 512);
    // 3) Local attention -> half
    local_attn_kernel<<<SEQ, 256>>>(qkv, attn);
    // 4) Out-proj + residual(x) -> fp32 + half
    gemm_mma<1, true, true><<<dim3(512/128, SEQ/128), 256>>>(
        attn, wout_t, b_out, x, o_f, o_h, SEQ, 512, 512);
    // 5) FFN up + GELU -> half
    gemm_mma<2, false, true><<<dim3(2048/128, SEQ/128), 256>>>(
        o_h, w1_t, b1, nullptr, nullptr, f1, SEQ, 2048, 512);
    // 6) FFN down + residual(o) -> fp32 final
    gemm_mma<1, true, false><<<dim3(512/128, SEQ/128), 256>>>(
        f1, w2_t, b2, o_f, out, nullptr, SEQ, 512, 2048);
}

// round 4
// speedup vs baseline: 3.8605x; 1.6737x over previous
#include <cuda_runtime.h>
#include <cuda_fp16.h>
#include <math.h>
#include <cstdint>

#define SEQ 2048
#define DIM 512

// ---------------------------------------------------------------------------
// Scratch (no cudaMalloc allowed)
// ---------------------------------------------------------------------------
__device__ __align__(16) __half g_xn_h  [SEQ * DIM];
__device__ __align__(16) __half g_wqkv_h[512 * 1536];   // [K,N] half
__device__ __align__(16) __half g_wout_h[512 * 512];
__device__ __align__(16) __half g_w1_h  [512 * 2048];
__device__ __align__(16) __half g_w2_h  [2048 * 512];
__device__ __align__(16) __half g_qkv_h [SEQ * 1536];
__device__ __align__(16) __half g_attn_h[SEQ * DIM];
__device__ __align__(16) float  g_out_f [SEQ * DIM];
__device__ __align__(16) __half g_out_h [SEQ * DIM];
__device__ __align__(16) __half g_f1_h  [SEQ * 2048];

// ---------------------------------------------------------------------------
// PTX helpers (base sm_103: mma.sync + ldmatrix + cp.async)
// ---------------------------------------------------------------------------
__device__ __forceinline__ uint32_t smem_u32(const void* p) {
    uint32_t a;
    asm("{ .reg .u64 t; cvta.to.shared.u64 t, %1; cvt.u32.u64 %0, t; }"
        : "=r"(a) : "l"(p));
    return a;
}
#define CP_ASYNC16(dst, src) \
    asm volatile("cp.async.cg.shared.global [%0], [%1], 16;" :: "r"(dst), "l"(src))
#define CP_COMMIT()  asm volatile("cp.async.commit_group;" ::: "memory")
#define CP_WAIT1()   asm volatile("cp.async.wait_group 1;" ::: "memory")

__device__ __forceinline__ void ldsm_x4(uint32_t& r0, uint32_t& r1,
                                        uint32_t& r2, uint32_t& r3, uint32_t a) {
    asm volatile("ldmatrix.sync.aligned.m8n8.x4.shared.b16 {%0,%1,%2,%3}, [%4];"
        : "=r"(r0), "=r"(r1), "=r"(r2), "=r"(r3) : "r"(a));
}
__device__ __forceinline__ void ldsm_x4_t(uint32_t& r0, uint32_t& r1,
                                          uint32_t& r2, uint32_t& r3, uint32_t a) {
    asm volatile("ldmatrix.sync.aligned.m8n8.x4.trans.shared.b16 {%0,%1,%2,%3}, [%4];"
        : "=r"(r0), "=r"(r1), "=r"(r2), "=r"(r3) : "r"(a));
}
__device__ __forceinline__ void mma16816(float* c, const uint32_t* a, const uint32_t* b) {
    asm volatile("mma.sync.aligned.m16n8k16.row.col.f32.f16.f16.f32 "
        "{%0,%1,%2,%3}, {%4,%5,%6,%7}, {%8,%9}, {%0,%1,%2,%3};"
        : "+f"(c[0]), "+f"(c[1]), "+f"(c[2]), "+f"(c[3])
        : "r"(a[0]), "r"(a[1]), "r"(a[2]), "r"(a[3]), "r"(b[0]), "r"(b[1]));
}

// ---------------------------------------------------------------------------
// fp32 -> half convert (no transpose; n multiple of 1024)
// ---------------------------------------------------------------------------
__global__ void __launch_bounds__(256) convert_h_kernel(
    const float* __restrict__ in, __half* __restrict__ out, int n)
{
    int i = (blockIdx.x * 256 + threadIdx.x) * 4;
    if (i < n) {
        float4 v = *(const float4*)&in[i];
        __half2 h0 = __floats2half2_rn(v.x, v.y);
        __half2 h1 = __floats2half2_rn(v.z, v.w);
        uint2 u;
        u.x = *(uint32_t*)&h0;
        u.y = *(uint32_t*)&h1;
        *(uint2*)&out[i] = u;
    }
}

// ---------------------------------------------------------------------------
// LayerNorm -> half
// ---------------------------------------------------------------------------
__global__ void __launch_bounds__(256) ln_kernel(
    const float* __restrict__ x, const float* __restrict__ g,
    const float* __restrict__ b, __half* __restrict__ y)
{
    int s = blockIdx.x, tid = threadIdx.x;
    const float* xr = x + (size_t)s * DIM;
    float v0 = xr[tid], v1 = xr[tid + 256];
    float sum = v0 + v1, sq = v0 * v0 + v1 * v1;
    #pragma unroll
    for (int o = 16; o > 0; o >>= 1) {
        sum += __shfl_xor_sync(~0u, sum, o);
        sq  += __shfl_xor_sync(~0u, sq,  o);
    }
    __shared__ float ss[8], s2[8];
    int w = tid >> 5, l = tid & 31;
    if (l == 0) { ss[w] = sum; s2[w] = sq; }
    __syncthreads();
    float tot = 0.f, tot2 = 0.f;
    #pragma unroll
    for (int i = 0; i < 8; i++) { tot += ss[i]; tot2 += s2[i]; }
    float mu = tot * (1.0f / 512.0f);
    float inv = rsqrtf(tot2 * (1.0f / 512.0f) - mu * mu + 1e-5f);
    __half* yr = y + (size_t)s * DIM;
    yr[tid]       = __float2half((v0 - mu) * inv * g[tid]       + b[tid]);
    yr[tid + 256] = __float2half((v1 - mu) * inv * g[tid + 256] + b[tid + 256]);
}

// ---------------------------------------------------------------------------
// HMMA GEMM: C[M,N] = A_h[M,K] @ B_h[K,N], fp32 accum.
// BM x 128 CTA tile, BK=32, 8 warps (2x4), 3-stage cp.async pipeline.
// B fragments via ldmatrix.x4.trans from row-major [K,N] smem tile.
// EPI: 0 = +bias ; 1 = +bias +res ; 2 = gelu(+bias)
// ---------------------------------------------------------------------------
template<int BM, int EPI, bool WF32, bool WH>
__global__ void __launch_bounds__(256) gemm_mma(
    const __half* __restrict__ A, const __half* __restrict__ B,
    const float* __restrict__ bias, const float* __restrict__ res,
    float* __restrict__ C, __half* __restrict__ Ch,
    int M, int N, int K)
{
    constexpr int TM   = BM / 2;        // warp rows (2x4 warp grid)
    constexpr int NI   = TM / 16;
    constexpr int ASTR = 40;            // halfs per A smem row
    constexpr int BSTR = 136;           // halfs per B smem row
    constexpr int ASZ  = BM * ASTR * 2; // bytes/stage
    constexpr int BSZ  = 32 * BSTR * 2;
    constexpr int STG  = ASZ + BSZ;

    extern __shared__ char smem[];
    uint32_t sb = smem_u32(smem);

    int tid = threadIdx.x, wid = tid >> 5, lane = tid & 31;
    int bm = blockIdx.y * BM, bn = blockIdx.x * 128;
    int wm = wid >> 2, wn = wid & 3;

    const int nK = K / 32;

    auto load_stage = [&](int kt, int s) {
        #pragma unroll
        for (int i = 0; i < BM / 64; i++) {
            int v = tid + i * 256;             // A chunk id
            int r = v >> 2, c = v & 3;
            CP_ASYNC16(sb + s * STG + (r * ASTR + c * 8) * 2,
                       A + (size_t)(bm + r) * K + kt * 32 + c * 8);
        }
        #pragma unroll
        for (int i = 0; i < 2; i++) {
            int v = tid + i * 256;             // B chunk id
            int k = v >> 4, c = v & 15;
            CP_ASYNC16(sb + s * STG + ASZ + (k * BSTR + c * 8) * 2,
                       B + (size_t)(kt * 32 + k) * N + bn + c * 8);
        }
    };

    float acc[NI][4][4] = {};

    load_stage(0, 0); CP_COMMIT();
    load_stage(1, 1); CP_COMMIT();

    int aru = lane & 15, acu = (lane >> 4) << 3;   // A ldmatrix
    int bg = lane >> 3, br = lane & 7;             // B ldmatrix.trans

    for (int kt = 0; kt < nK; kt++) {
        int s = kt % 3;
        CP_WAIT1();
        __syncthreads();
        if (kt + 2 < nK) load_stage(kt + 2, (kt + 2) % 3);
        CP_COMMIT();

        #pragma unroll
        for (int kk = 0; kk < 32; kk += 16) {
            uint32_t af[NI][4], bf[4][2];
            #pragma unroll
            for (int i = 0; i < NI; i++) {
                uint32_t addr = sb + s * STG +
                    ((wm * TM + i * 16 + aru) * ASTR + kk + acu) * 2;
                ldsm_x4(af[i][0], af[i][1], af[i][2], af[i][3], addr);
            }
            #pragma unroll
            for (int j2 = 0; j2 < 2; j2++) {
                uint32_t addr = sb + s * STG + ASZ +
                    ((kk + (bg & 1) * 8 + br) * BSTR +
                     wn * 32 + j2 * 16 + (bg >> 1) * 8) * 2;
                uint32_t r0, r1, r2, r3;
                ldsm_x4_t(r0, r1, r2, r3, addr);
                bf[j2 * 2][0] = r0;     bf[j2 * 2][1] = r1;
                bf[j2 * 2 + 1][0] = r2; bf[j2 * 2 + 1][1] = r3;
            }
            #pragma unroll
            for (int i = 0; i < NI; i++)
                #pragma unroll
                for (int j = 0; j < 4; j++)
                    mma16816(acc[i][j], af[i], bf[j]);
        }
        __syncthreads();
    }

    int tq = lane >> 2, tr = lane & 3;
    #pragma unroll
    for (int i = 0; i < NI; i++) {
        int row = bm + wm * TM + i * 16 + tq;
        #pragma unroll
        for (int j = 0; j < 4; j++) {
            int col = bn + wn * 32 + j * 8 + tr * 2;
            float b0 = bias[col], b1 = bias[col + 1];
            float v0 = acc[i][j][0] + b0, v1 = acc[i][j][1] + b1;
            float v2 = acc[i][j][2] + b0, v3 = acc[i][j][3] + b1;
            size_t p0 = (size_t)row * N + col;
            size_t p1 = (size_t)(row + 8) * N + col;
            if (EPI == 1) {
                float2 r0 = *(const float2*)&res[p0];
                float2 r1 = *(const float2*)&res[p1];
                v0 += r0.x; v1 += r0.y; v2 += r1.x; v3 += r1.y;
            }
            if (EPI == 2) {
                v0 = 0.5f * v0 * (1.0f + erff(v0 * 0.70710678118654752f));
                v1 = 0.5f * v1 * (1.0f + erff(v1 * 0.70710678118654752f));
                v2 = 0.5f * v2 * (1.0f + erff(v2 * 0.70710678118654752f));
                v3 = 0.5f * v3 * (1.0f + erff(v3 * 0.70710678118654752f));
            }
            if (WF32) {
                *(float2*)&C[p0] = make_float2(v0, v1);
                *(float2*)&C[p1] = make_float2(v2, v3);
            }
            if (WH) {
                *(__half2*)&Ch[p0] = __floats2half2_rn(v0, v1);
                *(__half2*)&Ch[p1] = __floats2half2_rn(v2, v3);
            }
        }
    }
}

// ---------------------------------------------------------------------------
// Local attention v2: SMEM-tiled. Block = (64-query tile, head).
// k window XOR-swizzled (16B chunks) -> conflict-free per-lane row reads.
// OOB positions zero-filled -> zero-pad softmax semantics automatic.
// ---------------------------------------------------------------------------
#define TS 64
#define WINP 192   // TS + 128 positions

__global__ void __launch_bounds__(256) attn2_kernel(
    const __half* __restrict__ qkv, __half* __restrict__ attn_out)
{
    extern __shared__ char sm[];
    char*   ksb = sm;                         // WINP rows x 128B swizzled
    __half* vs  = (__half*)(sm + WINP * 128); // WINP x 64
    __half* qs  = (__half*)(sm + WINP * 128 + WINP * 64 * 2); // 64 x 64
    float*  sc  = (float*)(sm + WINP * 128 + WINP * 64 * 2 + 64 * 64 * 2);

    int h = blockIdx.y;
    int s0 = blockIdx.x * TS;
    int tid = threadIdx.x, wid = tid >> 5, lane = tid & 31;

    // stage k, v (1536 16B-chunks each)
    for (int i = tid; i < WINP * 8; i += 256) {
        int p = i >> 3, c = i & 7;
        int t = s0 - 64 + p;
        uint4 kd = make_uint4(0, 0, 0, 0), vd = make_uint4(0, 0, 0, 0);
        if (t >= 0 && t < SEQ) {
            kd = *(const uint4*)&qkv[(size_t)t * 1536 + 512  + h * 64 + c * 8];
            vd = *(const uint4*)&qkv[(size_t)t * 1536 + 1024 + h * 64 + c * 8];
        }
        *(uint4*)(ksb + p * 128 + ((c ^ (p & 7)) * 16)) = kd;
        *(uint4*)(vs + p * 64 + c * 8) = vd;
    }
    // stage q (512 chunks)
    for (int i = tid; i < TS * 8; i += 256) {
        int r = i >> 3, c = i & 7;
        *(uint4*)(qs + r * 64 + c * 8) =
            *(const uint4*)&qkv[(size_t)(s0 + r) * 1536 + h * 64 + c * 8];
    }
    __syncthreads();

    float* scw = sc + wid * 132;

    for (int qi = wid * 8; qi < wid * 8 + 8; qi++) {
        // scores: lane owns j = lane + 32m
        #pragma unroll
        for (int m = 0; m < 5; m++) {
            int j = lane + m * 32;
            if (j < 129) {
                int p = qi + j;
                float dot = 0.0f;
                #pragma unroll
                for (int c = 0; c < 8; c++) {
                    uint4 kd = *(const uint4*)(ksb + p * 128 + ((c ^ (p & 7)) * 16));
                    uint4 qd = *(const uint4*)(qs + qi * 64 + c * 8);
                    const __half2* k2 = (const __half2*)&kd;
                    const __half2* q2 = (const __half2*)&qd;
                    #pragma unroll
                    for (int e = 0; e < 4; e++) {
                        float2 kf = __half22float2(k2[e]);
                        float2 qf = __half22float2(q2[e]);
                        dot += qf.x * kf.x + qf.y * kf.y;
                    }
                }
                scw[j] = dot * 0.125f;
            }
        }
        __syncwarp();

        float mx = -1e30f;
        for (int j = lane; j < 129; j += 32) mx = fmaxf(mx, scw[j]);
        #pragma unroll
        for (int o = 16; o > 0; o >>= 1) mx = fmaxf(mx, __shfl_xor_sync(~0u, mx, o));

        float sum = 0.0f;
        for (int j = lane; j < 129; j += 32) {
            float e = __expf(scw[j] - mx);
            scw[j] = e;
            sum += e;
        }
        #pragma unroll
        for (int o = 16; o > 0; o >>= 1) sum += __shfl_xor_sync(~0u, sum, o);
        float inv = 1.0f / sum;
        __syncwarp();

        // weighted v: lane owns dims 2*lane, 2*lane+1
        float o0 = 0.0f, o1 = 0.0f;
        #pragma unroll 4
        for (int j = 0; j < 129; j++) {
            float pr = scw[j];
            float2 vf = __half22float2(*(const __half2*)(vs + (qi + j) * 64 + lane * 2));
            o0 = fmaf(pr, vf.x, o0);
            o1 = fmaf(pr, vf.y, o1);
        }
        *(__half2*)&attn_out[(size_t)(s0 + qi) * DIM + h * 64 + lane * 2] =
            __floats2half2_rn(o0 * inv, o1 * inv);
        __syncwarp();
    }
}

// ---------------------------------------------------------------------------
extern "C" void kernel_launch(void* const* d_in, const int* in_sizes, int n_in,
                              void* d_out, int out_size)
{
    const float* x     = (const float*)d_in[0];
    const float* w_qkv = (const float*)d_in[1];
    const float* b_qkv = (const float*)d_in[2];
    const float* w_out = (const float*)d_in[3];
    const float* b_out = (const float*)d_in[4];
    const float* ln_g  = (const float*)d_in[5];
    const float* ln_b  = (const float*)d_in[6];
    const float* w1    = (const float*)d_in[7];
    const float* b1    = (const float*)d_in[8];
    const float* w2    = (const float*)d_in[9];
    const float* b2    = (const float*)d_in[10];
    float* out = (float*)d_out;

    __half *xn, *wqkv, *wout, *w1h, *w2h, *qkv, *attn, *o_h, *f1;
    float *o_f;
    cudaGetSymbolAddress((void**)&xn,   g_xn_h);
    cudaGetSymbolAddress((void**)&wqkv, g_wqkv_h);
    cudaGetSymbolAddress((void**)&wout, g_wout_h);
    cudaGetSymbolAddress((void**)&w1h,  g_w1_h);
    cudaGetSymbolAddress((void**)&w2h,  g_w2_h);
    cudaGetSymbolAddress((void**)&qkv,  g_qkv_h);
    cudaGetSymbolAddress((void**)&attn, g_attn_h);
    cudaGetSymbolAddress((void**)&o_f,  g_out_f);
    cudaGetSymbolAddress((void**)&o_h,  g_out_h);
    cudaGetSymbolAddress((void**)&f1,   g_f1_h);

    const int SM128 = 3 * (128 * 40 + 32 * 136) * 2;   // 56832
    const int SM64  = 3 * (64  * 40 + 32 * 136) * 2;   // 41472
    const int SMA   = WINP * 128 + WINP * 64 * 2 + 64 * 64 * 2 + 8 * 132 * 4;

    cudaFuncSetAttribute(gemm_mma<128, 0, false, true>,  cudaFuncAttributeMaxDynamicSharedMemorySize, SM128);
    cudaFuncSetAttribute(gemm_mma<128, 2, false, true>,  cudaFuncAttributeMaxDynamicSharedMemorySize, SM128);
    cudaFuncSetAttribute(gemm_mma<64,  1, true,  true>,  cudaFuncAttributeMaxDynamicSharedMemorySize, SM64);
    cudaFuncSetAttribute(gemm_mma<64,  1, true,  false>, cudaFuncAttributeMaxDynamicSharedMemorySize, SM64);
    cudaFuncSetAttribute(attn2_kernel, cudaFuncAttributeMaxDynamicSharedMemorySize, SMA);

    // Weight converts (fp32 -> half, [K,N] kept row-major)
    convert_h_kernel<<<512 * 1536 / 1024, 256>>>(w_qkv, wqkv, 512 * 1536);
    convert_h_kernel<<<512 * 512  / 1024, 256>>>(w_out, wout, 512 * 512);
    convert_h_kernel<<<512 * 2048 / 1024, 256>>>(w1,    w1h,  512 * 2048);
    convert_h_kernel<<<2048 * 512 / 1024, 256>>>(w2,    w2h,  2048 * 512);

    // 1) LayerNorm -> half
    ln_kernel<<<SEQ, 256>>>(x, ln_g, ln_b, xn);
    // 2) QKV: [2048,512] @ [512,1536]
    gemm_mma<128, 0, false, true><<<dim3(1536 / 128, SEQ / 128), 256, SM128>>>(
        xn, wqkv, b_qkv, nullptr, nullptr, qkv, SEQ, 1536, 512);
    // 3) Local attention
    attn2_kernel<<<dim3(SEQ / TS, 8), 256, SMA>>>(qkv, attn);
    // 4) Out-proj + residual(x)
    gemm_mma<64, 1, true, true><<<dim3(512 / 128, SEQ / 64), 256, SM64>>>(
        attn, wout, b_out, x, o_f, o_h, SEQ, 512, 512);
    // 5) FFN up + GELU
    gemm_mma<128, 2, false, true><<<dim3(2048 / 128, SEQ / 128), 256, SM128>>>(
        o_h, w1h, b1, nullptr, nullptr, f1, SEQ, 2048, 512);
    // 6) FFN down + residual(o)
    gemm_mma<64, 1, true, false><<<dim3(512 / 128, SEQ / 64), 256, SM64>>>(
        f1, w2h, b2, o_f, out, nullptr, SEQ, 512, 2048);
}

// round 5
// speedup vs baseline: 4.2075x; 1.0899x over previous
#include <cuda_runtime.h>
#include <cuda_fp16.h>
#include <math.h>
#include <cstdint>

#define SEQ 2048
#define DIM 512

// ---------------------------------------------------------------------------
// Scratch (no cudaMalloc allowed)
// ---------------------------------------------------------------------------
__device__ __align__(16) __half g_xn_h  [SEQ * DIM];
__device__ __align__(16) __half g_wqkv_h[512 * 1536];   // [K,N] half
__device__ __align__(16) __half g_wout_h[512 * 512];
__device__ __align__(16) __half g_w1_h  [512 * 2048];
__device__ __align__(16) __half g_w2_h  [2048 * 512];
__device__ __align__(16) __half g_qkv_h [SEQ * 1536];
__device__ __align__(16) __half g_attn_h[SEQ * DIM];
__device__ __align__(16) float  g_out_f [SEQ * DIM];
__device__ __align__(16) __half g_out_h [SEQ * DIM];
__device__ __align__(16) __half g_f1_h  [SEQ * 2048];

// ---------------------------------------------------------------------------
// PTX helpers (base sm_103: mma.sync + ldmatrix + cp.async)
// ---------------------------------------------------------------------------
__device__ __forceinline__ uint32_t smem_u32(const void* p) {
    uint32_t a;
    asm("{ .reg .u64 t; cvta.to.shared.u64 t, %1; cvt.u32.u64 %0, t; }"
        : "=r"(a) : "l"(p));
    return a;
}
#define CP_ASYNC16(dst, src) \
    asm volatile("cp.async.cg.shared.global [%0], [%1], 16;" :: "r"(dst), "l"(src))
#define CP_COMMIT()  asm volatile("cp.async.commit_group;" ::: "memory")
#define CP_WAIT2()   asm volatile("cp.async.wait_group 2;" ::: "memory")

__device__ __forceinline__ void ldsm_x4(uint32_t& r0, uint32_t& r1,
                                        uint32_t& r2, uint32_t& r3, uint32_t a) {
    asm volatile("ldmatrix.sync.aligned.m8n8.x4.shared.b16 {%0,%1,%2,%3}, [%4];"
        : "=r"(r0), "=r"(r1), "=r"(r2), "=r"(r3) : "r"(a));
}
__device__ __forceinline__ void ldsm_x4_t(uint32_t& r0, uint32_t& r1,
                                          uint32_t& r2, uint32_t& r3, uint32_t a) {
    asm volatile("ldmatrix.sync.aligned.m8n8.x4.trans.shared.b16 {%0,%1,%2,%3}, [%4];"
        : "=r"(r0), "=r"(r1), "=r"(r2), "=r"(r3) : "r"(a));
}
__device__ __forceinline__ void mma16816(float* c, const uint32_t* a, const uint32_t* b) {
    asm volatile("mma.sync.aligned.m16n8k16.row.col.f32.f16.f16.f32 "
        "{%0,%1,%2,%3}, {%4,%5,%6,%7}, {%8,%9}, {%0,%1,%2,%3};"
        : "+f"(c[0]), "+f"(c[1]), "+f"(c[2]), "+f"(c[3])
        : "r"(a[0]), "r"(a[1]), "r"(a[2]), "r"(a[3]), "r"(b[0]), "r"(b[1]));
}

// ---------------------------------------------------------------------------
// Fused fp32->half convert of all 4 weight matrices, one launch.
// Segment sizes in 1024-element blocks:
//   wqkv 768, wout 256, w1 1024, w2 1024   (total 3072 blocks)
// ---------------------------------------------------------------------------
__global__ void __launch_bounds__(256) convert_all_kernel(
    const float* __restrict__ wqkv, const float* __restrict__ wout,
    const float* __restrict__ w1,   const float* __restrict__ w2,
    __half* __restrict__ oqkv, __half* __restrict__ oout,
    __half* __restrict__ o1,   __half* __restrict__ o2)
{
    int b = blockIdx.x;
    const float* in; __half* out; int off;
    if      (b < 768)  { in = wqkv; out = oqkv; off = b; }
    else if (b < 1024) { in = wout; out = oout; off = b - 768; }
    else if (b < 2048) { in = w1;   out = o1;   off = b - 1024; }
    else               { in = w2;   out = o2;   off = b - 2048; }
    int i = off * 1024 + threadIdx.x * 4;
    float4 v = *(const float4*)&in[i];
    __half2 h0 = __floats2half2_rn(v.x, v.y);
    __half2 h1 = __floats2half2_rn(v.z, v.w);
    uint2 u;
    u.x = *(uint32_t*)&h0;
    u.y = *(uint32_t*)&h1;
    *(uint2*)&out[i] = u;
}

// ---------------------------------------------------------------------------
// LayerNorm -> half
// ---------------------------------------------------------------------------
__global__ void __launch_bounds__(256) ln_kernel(
    const float* __restrict__ x, const float* __restrict__ g,
    const float* __restrict__ b, __half* __restrict__ y)
{
    int s = blockIdx.x, tid = threadIdx.x;
    const float* xr = x + (size_t)s * DIM;
    float v0 = xr[tid], v1 = xr[tid + 256];
    float sum = v0 + v1, sq = v0 * v0 + v1 * v1;
    #pragma unroll
    for (int o = 16; o > 0; o >>= 1) {
        sum += __shfl_xor_sync(~0u, sum, o);
        sq  += __shfl_xor_sync(~0u, sq,  o);
    }
    __shared__ float ss[8], s2[8];
    int w = tid >> 5, l = tid & 31;
    if (l == 0) { ss[w] = sum; s2[w] = sq; }
    __syncthreads();
    float tot = 0.f, tot2 = 0.f;
    #pragma unroll
    for (int i = 0; i < 8; i++) { tot += ss[i]; tot2 += s2[i]; }
    float mu = tot * (1.0f / 512.0f);
    float inv = rsqrtf(tot2 * (1.0f / 512.0f) - mu * mu + 1e-5f);
    __half* yr = y + (size_t)s * DIM;
    yr[tid]       = __float2half((v0 - mu) * inv * g[tid]       + b[tid]);
    yr[tid + 256] = __float2half((v1 - mu) * inv * g[tid + 256] + b[tid + 256]);
}

// ---------------------------------------------------------------------------
// HMMA GEMM: C[M,N] = A_h[M,K] @ B_h[K,N], fp32 accum.
// BM x 128 CTA tile, BK=32, 8 warps (2x4), 4-stage cp.async pipeline,
// ONE __syncthreads per K-iteration.
// EPI: 0 = +bias ; 1 = +bias +res ; 2 = gelu(+bias)
// ---------------------------------------------------------------------------
template<int BM, int EPI, bool WF32, bool WH>
__global__ void __launch_bounds__(256) gemm_mma(
    const __half* __restrict__ A, const __half* __restrict__ B,
    const float* __restrict__ bias, const float* __restrict__ res,
    float* __restrict__ C, __half* __restrict__ Ch,
    int M, int N, int K)
{
    constexpr int TM   = BM / 2;
    constexpr int NI   = TM / 16;
    constexpr int ASTR = 40;
    constexpr int BSTR = 136;
    constexpr int ASZ  = BM * ASTR * 2;
    constexpr int BSZ  = 32 * BSTR * 2;
    constexpr int STG  = ASZ + BSZ;

    extern __shared__ char smem[];
    uint32_t sb = smem_u32(smem);

    int tid = threadIdx.x, wid = tid >> 5, lane = tid & 31;
    int bm = blockIdx.y * BM, bn = blockIdx.x * 128;
    int wm = wid >> 2, wn = wid & 3;

    const int nK = K / 32;

    auto load_stage = [&](int kt, int s) {
        #pragma unroll
        for (int i = 0; i < BM / 64; i++) {
            int v = tid + i * 256;
            int r = v >> 2, c = v & 3;
            CP_ASYNC16(sb + s * STG + (r * ASTR + c * 8) * 2,
                       A + (size_t)(bm + r) * K + kt * 32 + c * 8);
        }
        #pragma unroll
        for (int i = 0; i < 2; i++) {
            int v = tid + i * 256;
            int k = v >> 4, c = v & 15;
            CP_ASYNC16(sb + s * STG + ASZ + (k * BSTR + c * 8) * 2,
                       B + (size_t)(kt * 32 + k) * N + bn + c * 8);
        }
    };

    float acc[NI][4][4] = {};

    load_stage(0, 0); CP_COMMIT();
    load_stage(1, 1); CP_COMMIT();
    load_stage(2, 2); CP_COMMIT();

    int aru = lane & 15, acu = (lane >> 4) << 3;
    int bg = lane >> 3, br = lane & 7;

    for (int kt = 0; kt < nK; kt++) {
        int s = kt & 3;
        CP_WAIT2();
        __syncthreads();
        // safe: compute(kt-1) on stage (kt+3)&3 finished before this barrier
        if (kt + 3 < nK) load_stage(kt + 3, (kt + 3) & 3);
        CP_COMMIT();

        #pragma unroll
        for (int kk = 0; kk < 32; kk += 16) {
            uint32_t af[NI][4], bf[4][2];
            #pragma unroll
            for (int i = 0; i < NI; i++) {
                uint32_t addr = sb + s * STG +
                    ((wm * TM + i * 16 + aru) * ASTR + kk + acu) * 2;
                ldsm_x4(af[i][0], af[i][1], af[i][2], af[i][3], addr);
            }
            #pragma unroll
            for (int j2 = 0; j2 < 2; j2++) {
                uint32_t addr = sb + s * STG + ASZ +
                    ((kk + (bg & 1) * 8 + br) * BSTR +
                     wn * 32 + j2 * 16 + (bg >> 1) * 8) * 2;
                uint32_t r0, r1, r2, r3;
                ldsm_x4_t(r0, r1, r2, r3, addr);
                bf[j2 * 2][0] = r0;     bf[j2 * 2][1] = r1;
                bf[j2 * 2 + 1][0] = r2; bf[j2 * 2 + 1][1] = r3;
            }
            #pragma unroll
            for (int i = 0; i < NI; i++)
                #pragma unroll
                for (int j = 0; j < 4; j++)
                    mma16816(acc[i][j], af[i], bf[j]);
        }
    }

    int tq = lane >> 2, tr = lane & 3;
    #pragma unroll
    for (int i = 0; i < NI; i++) {
        int row = bm + wm * TM + i * 16 + tq;
        #pragma unroll
        for (int j = 0; j < 4; j++) {
            int col = bn + wn * 32 + j * 8 + tr * 2;
            float b0 = bias[col], b1 = bias[col + 1];
            float v0 = acc[i][j][0] + b0, v1 = acc[i][j][1] + b1;
            float v2 = acc[i][j][2] + b0, v3 = acc[i][j][3] + b1;
            size_t p0 = (size_t)row * N + col;
            size_t p1 = (size_t)(row + 8) * N + col;
            if (EPI == 1) {
                float2 r0 = *(const float2*)&res[p0];
                float2 r1 = *(const float2*)&res[p1];
                v0 += r0.x; v1 += r0.y; v2 += r1.x; v3 += r1.y;
            }
            if (EPI == 2) {
                v0 = 0.5f * v0 * (1.0f + erff(v0 * 0.70710678118654752f));
                v1 = 0.5f * v1 * (1.0f + erff(v1 * 0.70710678118654752f));
                v2 = 0.5f * v2 * (1.0f + erff(v2 * 0.70710678118654752f));
                v3 = 0.5f * v3 * (1.0f + erff(v3 * 0.70710678118654752f));
            }
            if (WF32) {
                *(float2*)&C[p0] = make_float2(v0, v1);
                *(float2*)&C[p1] = make_float2(v2, v3);
            }
            if (WH) {
                *(__half2*)&Ch[p0] = __floats2half2_rn(v0, v1);
                *(__half2*)&Ch[p1] = __floats2half2_rn(v2, v3);
            }
        }
    }
}

// ---------------------------------------------------------------------------
// Local attention: SMEM-tiled, q hoisted to registers per query.
// Block = (64-query tile, head). Zero-pad softmax semantics preserved.
// ---------------------------------------------------------------------------
#define TS 64
#define WINP 192

__global__ void __launch_bounds__(256) attn2_kernel(
    const __half* __restrict__ qkv, __half* __restrict__ attn_out)
{
    extern __shared__ char sm[];
    char*   ksb = sm;                                          // WINP x 128B swizzled
    __half* vs  = (__half*)(sm + WINP * 128);                  // WINP x 64
    __half* qs  = (__half*)(sm + WINP * 128 + WINP * 64 * 2);  // 64 x 64
    float*  sc  = (float*)(sm + WINP * 128 + WINP * 64 * 2 + 64 * 64 * 2);

    int h = blockIdx.y;
    int s0 = blockIdx.x * TS;
    int tid = threadIdx.x, wid = tid >> 5, lane = tid & 31;

    for (int i = tid; i < WINP * 8; i += 256) {
        int p = i >> 3, c = i & 7;
        int t = s0 - 64 + p;
        uint4 kd = make_uint4(0, 0, 0, 0), vd = make_uint4(0, 0, 0, 0);
        if (t >= 0 && t < SEQ) {
            kd = *(const uint4*)&qkv[(size_t)t * 1536 + 512  + h * 64 + c * 8];
            vd = *(const uint4*)&qkv[(size_t)t * 1536 + 1024 + h * 64 + c * 8];
        }
        *(uint4*)(ksb + p * 128 + ((c ^ (p & 7)) * 16)) = kd;
        *(uint4*)(vs + p * 64 + c * 8) = vd;
    }
    for (int i = tid; i < TS * 8; i += 256) {
        int r = i >> 3, c = i & 7;
        *(uint4*)(qs + r * 64 + c * 8) =
            *(const uint4*)&qkv[(size_t)(s0 + r) * 1536 + h * 64 + c * 8];
    }
    __syncthreads();

    float* scw = sc + wid * 132;

    for (int qi = wid * 8; qi < wid * 8 + 8; qi++) {
        // hoist q row into registers once
        uint4 qd[8];
        #pragma unroll
        for (int c = 0; c < 8; c++)
            qd[c] = *(const uint4*)(qs + qi * 64 + c * 8);

        #pragma unroll
        for (int m = 0; m < 5; m++) {
            int j = lane + m * 32;
            if (j < 129) {
                int p = qi + j;
                float dot = 0.0f;
                #pragma unroll
                for (int c = 0; c < 8; c++) {
                    uint4 kd = *(const uint4*)(ksb + p * 128 + ((c ^ (p & 7)) * 16));
                    const __half2* k2 = (const __half2*)&kd;
                    const __half2* q2 = (const __half2*)&qd[c];
                    #pragma unroll
                    for (int e = 0; e < 4; e++) {
                        float2 kf = __half22float2(k2[e]);
                        float2 qf = __half22float2(q2[e]);
                        dot += qf.x * kf.x + qf.y * kf.y;
                    }
                }
                scw[j] = dot * 0.125f;
            }
        }
        __syncwarp();

        float mx = -1e30f;
        for (int j = lane; j < 129; j += 32) mx = fmaxf(mx, scw[j]);
        #pragma unroll
        for (int o = 16; o > 0; o >>= 1) mx = fmaxf(mx, __shfl_xor_sync(~0u, mx, o));

        float sum = 0.0f;
        for (int j = lane; j < 129; j += 32) {
            float e = __expf(scw[j] - mx);
            scw[j] = e;
            sum += e;
        }
        #pragma unroll
        for (int o = 16; o > 0; o >>= 1) sum += __shfl_xor_sync(~0u, sum, o);
        float inv = 1.0f / sum;
        __syncwarp();

        float o0 = 0.0f, o1 = 0.0f;
        #pragma unroll 4
        for (int j = 0; j < 129; j++) {
            float pr = scw[j];
            float2 vf = __half22float2(*(const __half2*)(vs + (qi + j) * 64 + lane * 2));
            o0 = fmaf(pr, vf.x, o0);
            o1 = fmaf(pr, vf.y, o1);
        }
        *(__half2*)&attn_out[(size_t)(s0 + qi) * DIM + h * 64 + lane * 2] =
            __floats2half2_rn(o0 * inv, o1 * inv);
        __syncwarp();
    }
}

// ---------------------------------------------------------------------------
extern "C" void kernel_launch(void* const* d_in, const int* in_sizes, int n_in,
                              void* d_out, int out_size)
{
    const float* x     = (const float*)d_in[0];
    const float* w_qkv = (const float*)d_in[1];
    const float* b_qkv = (const float*)d_in[2];
    const float* w_out = (const float*)d_in[3];
    const float* b_out = (const float*)d_in[4];
    const float* ln_g  = (const float*)d_in[5];
    const float* ln_b  = (const float*)d_in[6];
    const float* w1    = (const float*)d_in[7];
    const float* b1    = (const float*)d_in[8];
    const float* w2    = (const float*)d_in[9];
    const float* b2    = (const float*)d_in[10];
    float* out = (float*)d_out;

    __half *xn, *wqkv, *wout, *w1h, *w2h, *qkv, *attn, *o_h, *f1;
    float *o_f;
    cudaGetSymbolAddress((void**)&xn,   g_xn_h);
    cudaGetSymbolAddress((void**)&wqkv, g_wqkv_h);
    cudaGetSymbolAddress((void**)&wout, g_wout_h);
    cudaGetSymbolAddress((void**)&w1h,  g_w1_h);
    cudaGetSymbolAddress((void**)&w2h,  g_w2_h);
    cudaGetSymbolAddress((void**)&qkv,  g_qkv_h);
    cudaGetSymbolAddress((void**)&attn, g_attn_h);
    cudaGetSymbolAddress((void**)&o_f,  g_out_f);
    cudaGetSymbolAddress((void**)&o_h,  g_out_h);
    cudaGetSymbolAddress((void**)&f1,   g_f1_h);

    const int SM128 = 4 * (128 * 40 + 32 * 136) * 2;   // 75776
    const int SM64  = 4 * (64  * 40 + 32 * 136) * 2;   // 55296
    const int SMA   = WINP * 128 + WINP * 64 * 2 + 64 * 64 * 2 + 8 * 132 * 4;

    cudaFuncSetAttribute(gemm_mma<128, 0, false, true>,  cudaFuncAttributeMaxDynamicSharedMemorySize, SM128);
    cudaFuncSetAttribute(gemm_mma<128, 2, false, true>,  cudaFuncAttributeMaxDynamicSharedMemorySize, SM128);
    cudaFuncSetAttribute(gemm_mma<64,  1, true,  true>,  cudaFuncAttributeMaxDynamicSharedMemorySize, SM64);
    cudaFuncSetAttribute(gemm_mma<64,  1, true,  false>, cudaFuncAttributeMaxDynamicSharedMemorySize, SM64);
    cudaFuncSetAttribute(attn2_kernel, cudaFuncAttributeMaxDynamicSharedMemorySize, SMA);

    // Weight converts, single launch
    convert_all_kernel<<<3072, 256>>>(w_qkv, w_out, w1, w2, wqkv, wout, w1h, w2h);

    // 1) LayerNorm -> half
    ln_kernel<<<SEQ, 256>>>(x, ln_g, ln_b, xn);
    // 2) QKV
    gemm_mma<128, 0, false, true><<<dim3(1536 / 128, SEQ / 128), 256, SM128>>>(
        xn, wqkv, b_qkv, nullptr, nullptr, qkv, SEQ, 1536, 512);
    // 3) Local attention
    attn2_kernel<<<dim3(SEQ / TS, 8), 256, SMA>>>(qkv, attn);
    // 4) Out-proj + residual(x)
    gemm_mma<64, 1, true, true><<<dim3(512 / 128, SEQ / 64), 256, SM64>>>(
        attn, wout, b_out, x, o_f, o_h, SEQ, 512, 512);
    // 5) FFN up + GELU
    gemm_mma<128, 2, false, true><<<dim3(2048 / 128, SEQ / 128), 256, SM128>>>(
        o_h, w1h, b1, nullptr, nullptr, f1, SEQ, 2048, 512);
    // 6) FFN down + residual(o)
    gemm_mma<64, 1, true, false><<<dim3(512 / 128, SEQ / 64), 256, SM64>>>(
        f1, w2h, b2, o_f, out, nullptr, SEQ, 512, 2048);
}

// round 6
// speedup vs baseline: 5.4739x; 1.3010x over previous
#include <cuda_runtime.h>
#include <cuda_fp16.h>
#include <math.h>
#include <cstdint>

#define SEQ 2048
#define DIM 512

// ---------------------------------------------------------------------------
// Scratch (no cudaMalloc allowed)
// ---------------------------------------------------------------------------
__device__ __align__(16) __half g_xn_h  [SEQ * DIM];
__device__ __align__(16) __half g_wqkv_h[512 * 1536];
__device__ __align__(16) __half g_wout_h[512 * 512];
__device__ __align__(16) __half g_w1_h  [512 * 2048];
__device__ __align__(16) __half g_w2_h  [2048 * 512];
__device__ __align__(16) __half g_qkv_h [SEQ * 1536];
__device__ __align__(16) __half g_attn_h[SEQ * DIM];
__device__ __align__(16) float  g_out_f [SEQ * DIM];
__device__ __align__(16) __half g_out_h [SEQ * DIM];
__device__ __align__(16) __half g_f1_h  [SEQ * 2048];

// ---------------------------------------------------------------------------
// PTX helpers
// ---------------------------------------------------------------------------
__device__ __forceinline__ uint32_t smem_u32(const void* p) {
    uint32_t a;
    asm("{ .reg .u64 t; cvta.to.shared.u64 t, %1; cvt.u32.u64 %0, t; }"
        : "=r"(a) : "l"(p));
    return a;
}
#define CP_ASYNC16(dst, src) \
    asm volatile("cp.async.cg.shared.global [%0], [%1], 16;" :: "r"(dst), "l"(src))
#define CP_COMMIT()  asm volatile("cp.async.commit_group;" ::: "memory")
#define CP_WAIT2()   asm volatile("cp.async.wait_group 2;" ::: "memory")

__device__ __forceinline__ void ldsm_x4(uint32_t& r0, uint32_t& r1,
                                        uint32_t& r2, uint32_t& r3, uint32_t a) {
    asm volatile("ldmatrix.sync.aligned.m8n8.x4.shared.b16 {%0,%1,%2,%3}, [%4];"
        : "=r"(r0), "=r"(r1), "=r"(r2), "=r"(r3) : "r"(a));
}
__device__ __forceinline__ void ldsm_x2(uint32_t& r0, uint32_t& r1, uint32_t a) {
    asm volatile("ldmatrix.sync.aligned.m8n8.x2.shared.b16 {%0,%1}, [%2];"
        : "=r"(r0), "=r"(r1) : "r"(a));
}
__device__ __forceinline__ void ldsm_x4_t(uint32_t& r0, uint32_t& r1,
                                          uint32_t& r2, uint32_t& r3, uint32_t a) {
    asm volatile("ldmatrix.sync.aligned.m8n8.x4.trans.shared.b16 {%0,%1,%2,%3}, [%4];"
        : "=r"(r0), "=r"(r1), "=r"(r2), "=r"(r3) : "r"(a));
}
__device__ __forceinline__ void mma16816(float* c, const uint32_t* a, const uint32_t* b) {
    asm volatile("mma.sync.aligned.m16n8k16.row.col.f32.f16.f16.f32 "
        "{%0,%1,%2,%3}, {%4,%5,%6,%7}, {%8,%9}, {%0,%1,%2,%3};"
        : "+f"(c[0]), "+f"(c[1]), "+f"(c[2]), "+f"(c[3])
        : "r"(a[0]), "r"(a[1]), "r"(a[2]), "r"(a[3]), "r"(b[0]), "r"(b[1]));
}

// ---------------------------------------------------------------------------
// Fused fp32->half convert of all 4 weight matrices, one launch.
// ---------------------------------------------------------------------------
__global__ void __launch_bounds__(256) convert_all_kernel(
    const float* __restrict__ wqkv, const float* __restrict__ wout,
    const float* __restrict__ w1,   const float* __restrict__ w2,
    __half* __restrict__ oqkv, __half* __restrict__ oout,
    __half* __restrict__ o1,   __half* __restrict__ o2)
{
    int b = blockIdx.x;
    const float* in; __half* out; int off;
    if      (b < 768)  { in = wqkv; out = oqkv; off = b; }
    else if (b < 1024) { in = wout; out = oout; off = b - 768; }
    else if (b < 2048) { in = w1;   out = o1;   off = b - 1024; }
    else               { in = w2;   out = o2;   off = b - 2048; }
    int i = off * 1024 + threadIdx.x * 4;
    float4 v = *(const float4*)&in[i];
    __half2 h0 = __floats2half2_rn(v.x, v.y);
    __half2 h1 = __floats2half2_rn(v.z, v.w);
    uint2 u;
    u.x = *(uint32_t*)&h0;
    u.y = *(uint32_t*)&h1;
    *(uint2*)&out[i] = u;
}

// ---------------------------------------------------------------------------
// LayerNorm -> half
// ---------------------------------------------------------------------------
__global__ void __launch_bounds__(256) ln_kernel(
    const float* __restrict__ x, const float* __restrict__ g,
    const float* __restrict__ b, __half* __restrict__ y)
{
    int s = blockIdx.x, tid = threadIdx.x;
    const float* xr = x + (size_t)s * DIM;
    float v0 = xr[tid], v1 = xr[tid + 256];
    float sum = v0 + v1, sq = v0 * v0 + v1 * v1;
    #pragma unroll
    for (int o = 16; o > 0; o >>= 1) {
        sum += __shfl_xor_sync(~0u, sum, o);
        sq  += __shfl_xor_sync(~0u, sq,  o);
    }
    __shared__ float ss[8], s2[8];
    int w = tid >> 5, l = tid & 31;
    if (l == 0) { ss[w] = sum; s2[w] = sq; }
    __syncthreads();
    float tot = 0.f, tot2 = 0.f;
    #pragma unroll
    for (int i = 0; i < 8; i++) { tot += ss[i]; tot2 += s2[i]; }
    float mu = tot * (1.0f / 512.0f);
    float inv = rsqrtf(tot2 * (1.0f / 512.0f) - mu * mu + 1e-5f);
    __half* yr = y + (size_t)s * DIM;
    yr[tid]       = __float2half((v0 - mu) * inv * g[tid]       + b[tid]);
    yr[tid + 256] = __float2half((v1 - mu) * inv * g[tid + 256] + b[tid + 256]);
}

// ---------------------------------------------------------------------------
// HMMA GEMM (unchanged from round 5)
// ---------------------------------------------------------------------------
template<int BM, int EPI, bool WF32, bool WH>
__global__ void __launch_bounds__(256) gemm_mma(
    const __half* __restrict__ A, const __half* __restrict__ B,
    const float* __restrict__ bias, const float* __restrict__ res,
    float* __restrict__ C, __half* __restrict__ Ch,
    int M, int N, int K)
{
    constexpr int TM   = BM / 2;
    constexpr int NI   = TM / 16;
    constexpr int ASTR = 40;
    constexpr int BSTR = 136;
    constexpr int ASZ  = BM * ASTR * 2;
    constexpr int BSZ  = 32 * BSTR * 2;
    constexpr int STG  = ASZ + BSZ;

    extern __shared__ char smem[];
    uint32_t sb = smem_u32(smem);

    int tid = threadIdx.x, wid = tid >> 5, lane = tid & 31;
    int bm = blockIdx.y * BM, bn = blockIdx.x * 128;
    int wm = wid >> 2, wn = wid & 3;

    const int nK = K / 32;

    auto load_stage = [&](int kt, int s) {
        #pragma unroll
        for (int i = 0; i < BM / 64; i++) {
            int v = tid + i * 256;
            int r = v >> 2, c = v & 3;
            CP_ASYNC16(sb + s * STG + (r * ASTR + c * 8) * 2,
                       A + (size_t)(bm + r) * K + kt * 32 + c * 8);
        }
        #pragma unroll
        for (int i = 0; i < 2; i++) {
            int v = tid + i * 256;
            int k = v >> 4, c = v & 15;
            CP_ASYNC16(sb + s * STG + ASZ + (k * BSTR + c * 8) * 2,
                       B + (size_t)(kt * 32 + k) * N + bn + c * 8);
        }
    };

    float acc[NI][4][4] = {};

    load_stage(0, 0); CP_COMMIT();
    load_stage(1, 1); CP_COMMIT();
    load_stage(2, 2); CP_COMMIT();

    int aru = lane & 15, acu = (lane >> 4) << 3;
    int bg = lane >> 3, br = lane & 7;

    for (int kt = 0; kt < nK; kt++) {
        int s = kt & 3;
        CP_WAIT2();
        __syncthreads();
        if (kt + 3 < nK) load_stage(kt + 3, (kt + 3) & 3);
        CP_COMMIT();

        #pragma unroll
        for (int kk = 0; kk < 32; kk += 16) {
            uint32_t af[NI][4], bf[4][2];
            #pragma unroll
            for (int i = 0; i < NI; i++) {
                uint32_t addr = sb + s * STG +
                    ((wm * TM + i * 16 + aru) * ASTR + kk + acu) * 2;
                ldsm_x4(af[i][0], af[i][1], af[i][2], af[i][3], addr);
            }
            #pragma unroll
            for (int j2 = 0; j2 < 2; j2++) {
                uint32_t addr = sb + s * STG + ASZ +
                    ((kk + (bg & 1) * 8 + br) * BSTR +
                     wn * 32 + j2 * 16 + (bg >> 1) * 8) * 2;
                uint32_t r0, r1, r2, r3;
                ldsm_x4_t(r0, r1, r2, r3, addr);
                bf[j2 * 2][0] = r0;     bf[j2 * 2][1] = r1;
                bf[j2 * 2 + 1][0] = r2; bf[j2 * 2 + 1][1] = r3;
            }
            #pragma unroll
            for (int i = 0; i < NI; i++)
                #pragma unroll
                for (int j = 0; j < 4; j++)
                    mma16816(acc[i][j], af[i], bf[j]);
        }
    }

    int tq = lane >> 2, tr = lane & 3;
    #pragma unroll
    for (int i = 0; i < NI; i++) {
        int row = bm + wm * TM + i * 16 + tq;
        #pragma unroll
        for (int j = 0; j < 4; j++) {
            int col = bn + wn * 32 + j * 8 + tr * 2;
            float b0 = bias[col], b1 = bias[col + 1];
            float v0 = acc[i][j][0] + b0, v1 = acc[i][j][1] + b1;
            float v2 = acc[i][j][2] + b0, v3 = acc[i][j][3] + b1;
            size_t p0 = (size_t)row * N + col;
            size_t p1 = (size_t)(row + 8) * N + col;
            if (EPI == 1) {
                float2 r0 = *(const float2*)&res[p0];
                float2 r1 = *(const float2*)&res[p1];
                v0 += r0.x; v1 += r0.y; v2 += r1.x; v3 += r1.y;
            }
            if (EPI == 2) {
                v0 = 0.5f * v0 * (1.0f + erff(v0 * 0.70710678118654752f));
                v1 = 0.5f * v1 * (1.0f + erff(v1 * 0.70710678118654752f));
                v2 = 0.5f * v2 * (1.0f + erff(v2 * 0.70710678118654752f));
                v3 = 0.5f * v3 * (1.0f + erff(v3 * 0.70710678118654752f));
            }
            if (WF32) {
                *(float2*)&C[p0] = make_float2(v0, v1);
                *(float2*)&C[p1] = make_float2(v2, v3);
            }
            if (WH) {
                *(__half2*)&Ch[p0] = __floats2half2_rn(v0, v1);
                *(__half2*)&Ch[p1] = __floats2half2_rn(v2, v3);
            }
        }
    }
}

// ---------------------------------------------------------------------------
// Tensor-core local attention. Block = (64-query tile, head), 8 warps.
//   S(64x192) = Q @ K^T  (HMMA; K rows zero-filled for OOB t -> score 0)
//   softmax rows with out-of-window = -1e30 (exp -> 0)
//   O(64x64)  = P @ V    (HMMA; P fp16)
// ---------------------------------------------------------------------------
#define TS 64
#define WINP 192
#define QSTR 72
#define KSTR 72
#define VSTR 72
#define SSTR 196   // floats
#define PSTR 200   // halfs

// smem byte offsets
#define OFF_Q 0
#define OFF_K (OFF_Q + 64 * QSTR * 2)            // 9216
#define OFF_V (OFF_K + WINP * KSTR * 2)          // 36864
#define OFF_S (OFF_V + WINP * VSTR * 2)          // 64512
#define OFF_P (OFF_S + 64 * SSTR * 4)            // 114688
#define SMA_TOTAL (OFF_P + 64 * PSTR * 2)        // 140288

__global__ void __launch_bounds__(256) attn3_kernel(
    const __half* __restrict__ qkv, __half* __restrict__ attn_out)
{
    extern __shared__ char sm[];
    __half* qs = (__half*)(sm + OFF_Q);
    __half* ks = (__half*)(sm + OFF_K);
    __half* vs = (__half*)(sm + OFF_V);
    float*  ss = (float*)(sm + OFF_S);
    __half* ps = (__half*)(sm + OFF_P);
    uint32_t qsb = smem_u32(qs), ksb = smem_u32(ks);
    uint32_t vsb = smem_u32(vs), psb = smem_u32(ps);

    int h = blockIdx.y;
    int s0 = blockIdx.x * TS;
    int tid = threadIdx.x, wid = tid >> 5, lane = tid & 31;

    // ---- stage K, V (192 rows x 64 halfs; OOB t -> zeros) ----
    for (int i = tid; i < WINP * 8; i += 256) {
        int p = i >> 3, c = i & 7;
        int t = s0 - 64 + p;
        uint4 kd = make_uint4(0, 0, 0, 0), vd = make_uint4(0, 0, 0, 0);
        if (t >= 0 && t < SEQ) {
            kd = *(const uint4*)&qkv[(size_t)t * 1536 + 512  + h * 64 + c * 8];
            vd = *(const uint4*)&qkv[(size_t)t * 1536 + 1024 + h * 64 + c * 8];
        }
        *(uint4*)(ks + p * KSTR + c * 8) = kd;
        *(uint4*)(vs + p * VSTR + c * 8) = vd;
    }
    // ---- stage Q (64 rows x 64 halfs) ----
    for (int i = tid; i < TS * 8; i += 256) {
        int r = i >> 3, c = i & 7;
        *(uint4*)(qs + r * QSTR + c * 8) =
            *(const uint4*)&qkv[(size_t)(s0 + r) * 1536 + h * 64 + c * 8];
    }
    __syncthreads();

    int aru = lane & 15, acu = (lane >> 4) << 3;
    int tq = lane >> 2, tr = lane & 3;

    // ---- S = Q @ K^T : warp grid 4x2 (16q x 96pos per warp) ----
    {
        int wq = wid >> 1, wp = wid & 1;
        int brr = lane & 7, bcc = ((lane >> 3) & 1) << 3;
        float acc_s[12][4] = {};
        #pragma unroll
        for (int kk = 0; kk < 64; kk += 16) {
            uint32_t af[4];
            ldsm_x4(af[0], af[1], af[2], af[3],
                    qsb + ((wq * 16 + aru) * QSTR + kk + acu) * 2);
            #pragma unroll
            for (int j = 0; j < 12; j++) {
                uint32_t bf[2];
                ldsm_x2(bf[0], bf[1],
                        ksb + ((wp * 96 + j * 8 + brr) * KSTR + kk + bcc) * 2);
                mma16816(acc_s[j], af, bf);
            }
        }
        // write S (scaled by 1/sqrt(64))
        #pragma unroll
        for (int j = 0; j < 12; j++) {
            int r = wq * 16 + tq, c = wp * 96 + j * 8 + tr * 2;
            *(float2*)&ss[r * SSTR + c] =
                make_float2(acc_s[j][0] * 0.125f, acc_s[j][1] * 0.125f);
            *(float2*)&ss[(r + 8) * SSTR + c] =
                make_float2(acc_s[j][2] * 0.125f, acc_s[j][3] * 0.125f);
        }
    }
    __syncthreads();

    // ---- softmax: warp w owns rows 8w..8w+7; window p in [r, r+128] ----
    for (int rr = 0; rr < 8; rr++) {
        int r = wid * 8 + rr;
        float v[6];
        #pragma unroll
        for (int i = 0; i < 6; i++) {
            int p = lane + i * 32;
            float sv = ss[r * SSTR + p];
            v[i] = (p >= r && p <= r + 128) ? sv : -1e30f;
        }
        float mx = v[0];
        #pragma unroll
        for (int i = 1; i < 6; i++) mx = fmaxf(mx, v[i]);
        #pragma unroll
        for (int o = 16; o > 0; o >>= 1) mx = fmaxf(mx, __shfl_xor_sync(~0u, mx, o));
        float e[6], sum = 0.0f;
        #pragma unroll
        for (int i = 0; i < 6; i++) { e[i] = __expf(v[i] - mx); sum += e[i]; }
        #pragma unroll
        for (int o = 16; o > 0; o >>= 1) sum += __shfl_xor_sync(~0u, sum, o);
        float inv = 1.0f / sum;
        #pragma unroll
        for (int i = 0; i < 6; i++)
            ps[r * PSTR + lane + i * 32] = __float2half(e[i] * inv);
    }
    __syncthreads();

    // ---- O = P @ V : warp grid 4x2 (16q x 32d per warp) ----
    {
        int wq2 = wid >> 1, wd = wid & 1;
        int bg = lane >> 3, br = lane & 7;
        float acc_o[4][4] = {};
        #pragma unroll
        for (int kk = 0; kk < WINP; kk += 16) {
            uint32_t af[4];
            ldsm_x4(af[0], af[1], af[2], af[3],
                    psb + ((wq2 * 16 + aru) * PSTR + kk + acu) * 2);
            #pragma unroll
            for (int j2 = 0; j2 < 2; j2++) {
                uint32_t r0, r1, r2, r3;
                ldsm_x4_t(r0, r1, r2, r3,
                          vsb + ((kk + (bg & 1) * 8 + br) * VSTR +
                                 wd * 32 + j2 * 16 + (bg >> 1) * 8) * 2);
                uint32_t b0[2] = {r0, r1}, b1[2] = {r2, r3};
                mma16816(acc_o[j2 * 2],     af, b0);
                mma16816(acc_o[j2 * 2 + 1], af, b1);
            }
        }
        int row = s0 + wq2 * 16 + tq;
        #pragma unroll
        for (int j = 0; j < 4; j++) {
            int col = h * 64 + wd * 32 + j * 8 + tr * 2;
            *(__half2*)&attn_out[(size_t)row * DIM + col] =
                __floats2half2_rn(acc_o[j][0], acc_o[j][1]);
            *(__half2*)&attn_out[(size_t)(row + 8) * DIM + col] =
                __floats2half2_rn(acc_o[j][2], acc_o[j][3]);
        }
    }
}

// ---------------------------------------------------------------------------
extern "C" void kernel_launch(void* const* d_in, const int* in_sizes, int n_in,
                              void* d_out, int out_size)
{
    const float* x     = (const float*)d_in[0];
    const float* w_qkv = (const float*)d_in[1];
    const float* b_qkv = (const float*)d_in[2];
    const float* w_out = (const float*)d_in[3];
    const float* b_out = (const float*)d_in[4];
    const float* ln_g  = (const float*)d_in[5];
    const float* ln_b  = (const float*)d_in[6];
    const float* w1    = (const float*)d_in[7];
    const float* b1    = (const float*)d_in[8];
    const float* w2    = (const float*)d_in[9];
    const float* b2    = (const float*)d_in[10];
    float* out = (float*)d_out;

    __half *xn, *wqkv, *wout, *w1h, *w2h, *qkv, *attn, *o_h, *f1;
    float *o_f;
    cudaGetSymbolAddress((void**)&xn,   g_xn_h);
    cudaGetSymbolAddress((void**)&wqkv, g_wqkv_h);
    cudaGetSymbolAddress((void**)&wout, g_wout_h);
    cudaGetSymbolAddress((void**)&w1h,  g_w1_h);
    cudaGetSymbolAddress((void**)&w2h,  g_w2_h);
    cudaGetSymbolAddress((void**)&qkv,  g_qkv_h);
    cudaGetSymbolAddress((void**)&attn, g_attn_h);
    cudaGetSymbolAddress((void**)&o_f,  g_out_f);
    cudaGetSymbolAddress((void**)&o_h,  g_out_h);
    cudaGetSymbolAddress((void**)&f1,   g_f1_h);

    const int SM128 = 4 * (128 * 40 + 32 * 136) * 2;
    const int SM64  = 4 * (64  * 40 + 32 * 136) * 2;

    cudaFuncSetAttribute(gemm_mma<128, 0, false, true>,  cudaFuncAttributeMaxDynamicSharedMemorySize, SM128);
    cudaFuncSetAttribute(gemm_mma<128, 2, false, true>,  cudaFuncAttributeMaxDynamicSharedMemorySize, SM128);
    cudaFuncSetAttribute(gemm_mma<64,  1, true,  true>,  cudaFuncAttributeMaxDynamicSharedMemorySize, SM64);
    cudaFuncSetAttribute(gemm_mma<64,  1, true,  false>, cudaFuncAttributeMaxDynamicSharedMemorySize, SM64);
    cudaFuncSetAttribute(attn3_kernel, cudaFuncAttributeMaxDynamicSharedMemorySize, SMA_TOTAL);

    convert_all_kernel<<<3072, 256>>>(w_qkv, w_out, w1, w2, wqkv, wout, w1h, w2h);

    ln_kernel<<<SEQ, 256>>>(x, ln_g, ln_b, xn);
    gemm_mma<128, 0, false, true><<<dim3(1536 / 128, SEQ / 128), 256, SM128>>>(
        xn, wqkv, b_qkv, nullptr, nullptr, qkv, SEQ, 1536, 512);
    attn3_kernel<<<dim3(SEQ / TS, 8), 256, SMA_TOTAL>>>(qkv, attn);
    gemm_mma<64, 1, true, true><<<dim3(512 / 128, SEQ / 64), 256, SM64>>>(
        attn, wout, b_out, x, o_f, o_h, SEQ, 512, 512);
    gemm_mma<128, 2, false, true><<<dim3(2048 / 128, SEQ / 128), 256, SM128>>>(
        o_h, w1h, b1, nullptr, nullptr, f1, SEQ, 2048, 512);
    gemm_mma<64, 1, true, false><<<dim3(512 / 128, SEQ / 64), 256, SM64>>>(
        f1, w2h, b2, o_f, out, nullptr, SEQ, 512, 2048);
}

// round 7
// speedup vs baseline: 5.4756x; 1.0003x over previous
#include <cuda_runtime.h>
#include <cuda_fp16.h>
#include <math.h>
#include <cstdint>

#define SEQ 2048
#define DIM 512

// ---------------------------------------------------------------------------
// Scratch (no cudaMalloc allowed)
// ---------------------------------------------------------------------------
__device__ __align__(16) __half g_xn_h  [SEQ * DIM];
__device__ __align__(16) __half g_wqkv_h[512 * 1536];
__device__ __align__(16) __half g_wout_h[512 * 512];
__device__ __align__(16) __half g_w1_h  [512 * 2048];
__device__ __align__(16) __half g_w2_h  [2048 * 512];
__device__ __align__(16) __half g_qkv_h [SEQ * 1536];
__device__ __align__(16) __half g_attn_h[SEQ * DIM];
__device__ __align__(16) float  g_out_f [SEQ * DIM];
__device__ __align__(16) __half g_out_h [SEQ * DIM];
__device__ __align__(16) __half g_f1_h  [SEQ * 2048];

// ---------------------------------------------------------------------------
// PTX helpers
// ---------------------------------------------------------------------------
__device__ __forceinline__ uint32_t smem_u32(const void* p) {
    uint32_t a;
    asm("{ .reg .u64 t; cvta.to.shared.u64 t, %1; cvt.u32.u64 %0, t; }"
        : "=r"(a) : "l"(p));
    return a;
}
#define CP_ASYNC16(dst, src) \
    asm volatile("cp.async.cg.shared.global [%0], [%1], 16;" :: "r"(dst), "l"(src))
#define CP_COMMIT()  asm volatile("cp.async.commit_group;" ::: "memory")
#define CP_WAIT2()   asm volatile("cp.async.wait_group 2;" ::: "memory")

__device__ __forceinline__ void ldsm_x4(uint32_t& r0, uint32_t& r1,
                                        uint32_t& r2, uint32_t& r3, uint32_t a) {
    asm volatile("ldmatrix.sync.aligned.m8n8.x4.shared.b16 {%0,%1,%2,%3}, [%4];"
        : "=r"(r0), "=r"(r1), "=r"(r2), "=r"(r3) : "r"(a));
}
__device__ __forceinline__ void ldsm_x2(uint32_t& r0, uint32_t& r1, uint32_t a) {
    asm volatile("ldmatrix.sync.aligned.m8n8.x2.shared.b16 {%0,%1}, [%2];"
        : "=r"(r0), "=r"(r1) : "r"(a));
}
__device__ __forceinline__ void ldsm_x4_t(uint32_t& r0, uint32_t& r1,
                                          uint32_t& r2, uint32_t& r3, uint32_t a) {
    asm volatile("ldmatrix.sync.aligned.m8n8.x4.trans.shared.b16 {%0,%1,%2,%3}, [%4];"
        : "=r"(r0), "=r"(r1), "=r"(r2), "=r"(r3) : "r"(a));
}
__device__ __forceinline__ void mma16816(float* c, const uint32_t* a, const uint32_t* b) {
    asm volatile("mma.sync.aligned.m16n8k16.row.col.f32.f16.f16.f32 "
        "{%0,%1,%2,%3}, {%4,%5,%6,%7}, {%8,%9}, {%0,%1,%2,%3};"
        : "+f"(c[0]), "+f"(c[1]), "+f"(c[2]), "+f"(c[3])
        : "r"(a[0]), "r"(a[1]), "r"(a[2]), "r"(a[3]), "r"(b[0]), "r"(b[1]));
}

// ---------------------------------------------------------------------------
// Fused fp32->half convert of all 4 weight matrices, one launch.
// ---------------------------------------------------------------------------
__global__ void __launch_bounds__(256) convert_all_kernel(
    const float* __restrict__ wqkv, const float* __restrict__ wout,
    const float* __restrict__ w1,   const float* __restrict__ w2,
    __half* __restrict__ oqkv, __half* __restrict__ oout,
    __half* __restrict__ o1,   __half* __restrict__ o2)
{
    int b = blockIdx.x;
    const float* in; __half* out; int off;
    if      (b < 768)  { in = wqkv; out = oqkv; off = b; }
    else if (b < 1024) { in = wout; out = oout; off = b - 768; }
    else if (b < 2048) { in = w1;   out = o1;   off = b - 1024; }
    else               { in = w2;   out = o2;   off = b - 2048; }
    int i = off * 1024 + threadIdx.x * 4;
    float4 v = *(const float4*)&in[i];
    __half2 h0 = __floats2half2_rn(v.x, v.y);
    __half2 h1 = __floats2half2_rn(v.z, v.w);
    uint2 u;
    u.x = *(uint32_t*)&h0;
    u.y = *(uint32_t*)&h1;
    *(uint2*)&out[i] = u;
}

// ---------------------------------------------------------------------------
// LayerNorm -> half
// ---------------------------------------------------------------------------
__global__ void __launch_bounds__(256) ln_kernel(
    const float* __restrict__ x, const float* __restrict__ g,
    const float* __restrict__ b, __half* __restrict__ y)
{
    int s = blockIdx.x, tid = threadIdx.x;
    const float* xr = x + (size_t)s * DIM;
    float v0 = xr[tid], v1 = xr[tid + 256];
    float sum = v0 + v1, sq = v0 * v0 + v1 * v1;
    #pragma unroll
    for (int o = 16; o > 0; o >>= 1) {
        sum += __shfl_xor_sync(~0u, sum, o);
        sq  += __shfl_xor_sync(~0u, sq,  o);
    }
    __shared__ float ss[8], s2[8];
    int w = tid >> 5, l = tid & 31;
    if (l == 0) { ss[w] = sum; s2[w] = sq; }
    __syncthreads();
    float tot = 0.f, tot2 = 0.f;
    #pragma unroll
    for (int i = 0; i < 8; i++) { tot += ss[i]; tot2 += s2[i]; }
    float mu = tot * (1.0f / 512.0f);
    float inv = rsqrtf(tot2 * (1.0f / 512.0f) - mu * mu + 1e-5f);
    __half* yr = y + (size_t)s * DIM;
    yr[tid]       = __float2half((v0 - mu) * inv * g[tid]       + b[tid]);
    yr[tid + 256] = __float2half((v1 - mu) * inv * g[tid + 256] + b[tid + 256]);
}

// ---------------------------------------------------------------------------
// HMMA GEMM (unchanged from round 5)
// ---------------------------------------------------------------------------
template<int BM, int EPI, bool WF32, bool WH>
__global__ void __launch_bounds__(256) gemm_mma(
    const __half* __restrict__ A, const __half* __restrict__ B,
    const float* __restrict__ bias, const float* __restrict__ res,
    float* __restrict__ C, __half* __restrict__ Ch,
    int M, int N, int K)
{
    constexpr int TM   = BM / 2;
    constexpr int NI   = TM / 16;
    constexpr int ASTR = 40;
    constexpr int BSTR = 136;
    constexpr int ASZ  = BM * ASTR * 2;
    constexpr int BSZ  = 32 * BSTR * 2;
    constexpr int STG  = ASZ + BSZ;

    extern __shared__ char smem[];
    uint32_t sb = smem_u32(smem);

    int tid = threadIdx.x, wid = tid >> 5, lane = tid & 31;
    int bm = blockIdx.y * BM, bn = blockIdx.x * 128;
    int wm = wid >> 2, wn = wid & 3;

    const int nK = K / 32;

    auto load_stage = [&](int kt, int s) {
        #pragma unroll
        for (int i = 0; i < BM / 64; i++) {
            int v = tid + i * 256;
            int r = v >> 2, c = v & 3;
            CP_ASYNC16(sb + s * STG + (r * ASTR + c * 8) * 2,
                       A + (size_t)(bm + r) * K + kt * 32 + c * 8);
        }
        #pragma unroll
        for (int i = 0; i < 2; i++) {
            int v = tid + i * 256;
            int k = v >> 4, c = v & 15;
            CP_ASYNC16(sb + s * STG + ASZ + (k * BSTR + c * 8) * 2,
                       B + (size_t)(kt * 32 + k) * N + bn + c * 8);
        }
    };

    float acc[NI][4][4] = {};

    load_stage(0, 0); CP_COMMIT();
    load_stage(1, 1); CP_COMMIT();
    load_stage(2, 2); CP_COMMIT();

    int aru = lane & 15, acu = (lane >> 4) << 3;
    int bg = lane >> 3, br = lane & 7;

    for (int kt = 0; kt < nK; kt++) {
        int s = kt & 3;
        CP_WAIT2();
        __syncthreads();
        if (kt + 3 < nK) load_stage(kt + 3, (kt + 3) & 3);
        CP_COMMIT();

        #pragma unroll
        for (int kk = 0; kk < 32; kk += 16) {
            uint32_t af[NI][4], bf[4][2];
            #pragma unroll
            for (int i = 0; i < NI; i++) {
                uint32_t addr = sb + s * STG +
                    ((wm * TM + i * 16 + aru) * ASTR + kk + acu) * 2;
                ldsm_x4(af[i][0], af[i][1], af[i][2], af[i][3], addr);
            }
            #pragma unroll
            for (int j2 = 0; j2 < 2; j2++) {
                uint32_t addr = sb + s * STG + ASZ +
                    ((kk + (bg & 1) * 8 + br) * BSTR +
                     wn * 32 + j2 * 16 + (bg >> 1) * 8) * 2;
                uint32_t r0, r1, r2, r3;
                ldsm_x4_t(r0, r1, r2, r3, addr);
                bf[j2 * 2][0] = r0;     bf[j2 * 2][1] = r1;
                bf[j2 * 2 + 1][0] = r2; bf[j2 * 2 + 1][1] = r3;
            }
            #pragma unroll
            for (int i = 0; i < NI; i++)
                #pragma unroll
                for (int j = 0; j < 4; j++)
                    mma16816(acc[i][j], af[i], bf[j]);
        }
    }

    int tq = lane >> 2, tr = lane & 3;
    #pragma unroll
    for (int i = 0; i < NI; i++) {
        int row = bm + wm * TM + i * 16 + tq;
        #pragma unroll
        for (int j = 0; j < 4; j++) {
            int col = bn + wn * 32 + j * 8 + tr * 2;
            float b0 = bias[col], b1 = bias[col + 1];
            float v0 = acc[i][j][0] + b0, v1 = acc[i][j][1] + b1;
            float v2 = acc[i][j][2] + b0, v3 = acc[i][j][3] + b1;
            size_t p0 = (size_t)row * N + col;
            size_t p1 = (size_t)(row + 8) * N + col;
            if (EPI == 1) {
                float2 r0 = *(const float2*)&res[p0];
                float2 r1 = *(const float2*)&res[p1];
                v0 += r0.x; v1 += r0.y; v2 += r1.x; v3 += r1.y;
            }
            if (EPI == 2) {
                v0 = 0.5f * v0 * (1.0f + erff(v0 * 0.70710678118654752f));
                v1 = 0.5f * v1 * (1.0f + erff(v1 * 0.70710678118654752f));
                v2 = 0.5f * v2 * (1.0f + erff(v2 * 0.70710678118654752f));
                v3 = 0.5f * v3 * (1.0f + erff(v3 * 0.70710678118654752f));
            }
            if (WF32) {
                *(float2*)&C[p0] = make_float2(v0, v1);
                *(float2*)&C[p1] = make_float2(v2, v3);
            }
            if (WH) {
                *(__half2*)&Ch[p0] = __floats2half2_rn(v0, v1);
                *(__half2*)&Ch[p1] = __floats2half2_rn(v2, v3);
            }
        }
    }
}

// ---------------------------------------------------------------------------
// Tensor-core local attention. Block = (64-query tile, head), 8 warps.
//   S(64x192) = Q @ K^T  (HMMA; K rows zero-filled for OOB t -> score 0)
//   softmax rows with out-of-window = -1e30 (exp -> 0)
//   O(64x64)  = P @ V    (HMMA; P fp16)
// ---------------------------------------------------------------------------
#define TS 64
#define WINP 192
#define QSTR 72
#define KSTR 72
#define VSTR 72
#define SSTR 196   // floats
#define PSTR 200   // halfs

// smem byte offsets
#define OFF_Q 0
#define OFF_K (OFF_Q + 64 * QSTR * 2)            // 9216
#define OFF_V (OFF_K + WINP * KSTR * 2)          // 36864
#define OFF_S (OFF_V + WINP * VSTR * 2)          // 64512
#define OFF_P (OFF_S + 64 * SSTR * 4)            // 114688
#define SMA_TOTAL (OFF_P + 64 * PSTR * 2)        // 140288

__global__ void __launch_bounds__(256) attn3_kernel(
    const __half* __restrict__ qkv, __half* __restrict__ attn_out)
{
    extern __shared__ char sm[];
    __half* qs = (__half*)(sm + OFF_Q);
    __half* ks = (__half*)(sm + OFF_K);
    __half* vs = (__half*)(sm + OFF_V);
    float*  ss = (float*)(sm + OFF_S);
    __half* ps = (__half*)(sm + OFF_P);
    uint32_t qsb = smem_u32(qs), ksb = smem_u32(ks);
    uint32_t vsb = smem_u32(vs), psb = smem_u32(ps);

    int h = blockIdx.y;
    int s0 = blockIdx.x * TS;
    int tid = threadIdx.x, wid = tid >> 5, lane = tid & 31;

    // ---- stage K, V (192 rows x 64 halfs; OOB t -> zeros) ----
    for (int i = tid; i < WINP * 8; i += 256) {
        int p = i >> 3, c = i & 7;
        int t = s0 - 64 + p;
        uint4 kd = make_uint4(0, 0, 0, 0), vd = make_uint4(0, 0, 0, 0);
        if (t >= 0 && t < SEQ) {
            kd = *(const uint4*)&qkv[(size_t)t * 1536 + 512  + h * 64 + c * 8];
            vd = *(const uint4*)&qkv[(size_t)t * 1536 + 1024 + h * 64 + c * 8];
        }
        *(uint4*)(ks + p * KSTR + c * 8) = kd;
        *(uint4*)(vs + p * VSTR + c * 8) = vd;
    }
    // ---- stage Q (64 rows x 64 halfs) ----
    for (int i = tid; i < TS * 8; i += 256) {
        int r = i >> 3, c = i & 7;
        *(uint4*)(qs + r * QSTR + c * 8) =
            *(const uint4*)&qkv[(size_t)(s0 + r) * 1536 + h * 64 + c * 8];
    }
    __syncthreads();

    int aru = lane & 15, acu = (lane >> 4) << 3;
    int tq = lane >> 2, tr = lane & 3;

    // ---- S = Q @ K^T : warp grid 4x2 (16q x 96pos per warp) ----
    {
        int wq = wid >> 1, wp = wid & 1;
        int brr = lane & 7, bcc = ((lane >> 3) & 1) << 3;
        float acc_s[12][4] = {};
        #pragma unroll
        for (int kk = 0; kk < 64; kk += 16) {
            uint32_t af[4];
            ldsm_x4(af[0], af[1], af[2], af[3],
                    qsb + ((wq * 16 + aru) * QSTR + kk + acu) * 2);
            #pragma unroll
            for (int j = 0; j < 12; j++) {
                uint32_t bf[2];
                ldsm_x2(bf[0], bf[1],
                        ksb + ((wp * 96 + j * 8 + brr) * KSTR + kk + bcc) * 2);
                mma16816(acc_s[j], af, bf);
            }
        }
        // write S (scaled by 1/sqrt(64))
        #pragma unroll
        for (int j = 0; j < 12; j++) {
            int r = wq * 16 + tq, c = wp * 96 + j * 8 + tr * 2;
            *(float2*)&ss[r * SSTR + c] =
                make_float2(acc_s[j][0] * 0.125f, acc_s[j][1] * 0.125f);
            *(float2*)&ss[(r + 8) * SSTR + c] =
                make_float2(acc_s[j][2] * 0.125f, acc_s[j][3] * 0.125f);
        }
    }
    __syncthreads();

    // ---- softmax: warp w owns rows 8w..8w+7; window p in [r, r+128] ----
    for (int rr = 0; rr < 8; rr++) {
        int r = wid * 8 + rr;
        float v[6];
        #pragma unroll
        for (int i = 0; i < 6; i++) {
            int p = lane + i * 32;
            float sv = ss[r * SSTR + p];
            v[i] = (p >= r && p <= r + 128) ? sv : -1e30f;
        }
        float mx = v[0];
        #pragma unroll
        for (int i = 1; i < 6; i++) mx = fmaxf(mx, v[i]);
        #pragma unroll
        for (int o = 16; o > 0; o >>= 1) mx = fmaxf(mx, __shfl_xor_sync(~0u, mx, o));
        float e[6], sum = 0.0f;
        #pragma unroll
        for (int i = 0; i < 6; i++) { e[i] = __expf(v[i] - mx); sum += e[i]; }
        #pragma unroll
        for (int o = 16; o > 0; o >>= 1) sum += __shfl_xor_sync(~0u, sum, o);
        float inv = 1.0f / sum;
        #pragma unroll
        for (int i = 0; i < 6; i++)
            ps[r * PSTR + lane + i * 32] = __float2half(e[i] * inv);
    }
    __syncthreads();

    // ---- O = P @ V : warp grid 4x2 (16q x 32d per warp) ----
    {
        int wq2 = wid >> 1, wd = wid & 1;
        int bg = lane >> 3, br = lane & 7;
        float acc_o[4][4] = {};
        #pragma unroll
        for (int kk = 0; kk < WINP; kk += 16) {
            uint32_t af[4];
            ldsm_x4(af[0], af[1], af[2], af[3],
                    psb + ((wq2 * 16 + aru) * PSTR + kk + acu) * 2);
            #pragma unroll
            for (int j2 = 0; j2 < 2; j2++) {
                uint32_t r0, r1, r2, r3;
                ldsm_x4_t(r0, r1, r2, r3,
                          vsb + ((kk + (bg & 1) * 8 + br) * VSTR +
                                 wd * 32 + j2 * 16 + (bg >> 1) * 8) * 2);
                uint32_t b0[2] = {r0, r1}, b1[2] = {r2, r3};
                mma16816(acc_o[j2 * 2],     af, b0);
                mma16816(acc_o[j2 * 2 + 1], af, b1);
            }
        }
        int row = s0 + wq2 * 16 + tq;
        #pragma unroll
        for (int j = 0; j < 4; j++) {
            int col = h * 64 + wd * 32 + j * 8 + tr * 2;
            *(__half2*)&attn_out[(size_t)row * DIM + col] =
                __floats2half2_rn(acc_o[j][0], acc_o[j][1]);
            *(__half2*)&attn_out[(size_t)(row + 8) * DIM + col] =
                __floats2half2_rn(acc_o[j][2], acc_o[j][3]);
        }
    }
}

// ---------------------------------------------------------------------------
extern "C" void kernel_launch(void* const* d_in, const int* in_sizes, int n_in,
                              void* d_out, int out_size)
{
    const float* x     = (const float*)d_in[0];
    const float* w_qkv = (const float*)d_in[1];
    const float* b_qkv = (const float*)d_in[2];
    const float* w_out = (const float*)d_in[3];
    const float* b_out = (const float*)d_in[4];
    const float* ln_g  = (const float*)d_in[5];
    const float* ln_b  = (const float*)d_in[6];
    const float* w1    = (const float*)d_in[7];
    const float* b1    = (const float*)d_in[8];
    const float* w2    = (const float*)d_in[9];
    const float* b2    = (const float*)d_in[10];
    float* out = (float*)d_out;

    __half *xn, *wqkv, *wout, *w1h, *w2h, *qkv, *attn, *o_h, *f1;
    float *o_f;
    cudaGetSymbolAddress((void**)&xn,   g_xn_h);
    cudaGetSymbolAddress((void**)&wqkv, g_wqkv_h);
    cudaGetSymbolAddress((void**)&wout, g_wout_h);
    cudaGetSymbolAddress((void**)&w1h,  g_w1_h);
    cudaGetSymbolAddress((void**)&w2h,  g_w2_h);
    cudaGetSymbolAddress((void**)&qkv,  g_qkv_h);
    cudaGetSymbolAddress((void**)&attn, g_attn_h);
    cudaGetSymbolAddress((void**)&o_f,  g_out_f);
    cudaGetSymbolAddress((void**)&o_h,  g_out_h);
    cudaGetSymbolAddress((void**)&f1,   g_f1_h);

    const int SM128 = 4 * (128 * 40 + 32 * 136) * 2;
    const int SM64  = 4 * (64  * 40 + 32 * 136) * 2;

    cudaFuncSetAttribute(gemm_mma<128, 0, false, true>,  cudaFuncAttributeMaxDynamicSharedMemorySize, SM128);
    cudaFuncSetAttribute(gemm_mma<128, 2, false, true>,  cudaFuncAttributeMaxDynamicSharedMemorySize, SM128);
    cudaFuncSetAttribute(gemm_mma<64,  1, true,  true>,  cudaFuncAttributeMaxDynamicSharedMemorySize, SM64);
    cudaFuncSetAttribute(gemm_mma<64,  1, true,  false>, cudaFuncAttributeMaxDynamicSharedMemorySize, SM64);
    cudaFuncSetAttribute(attn3_kernel, cudaFuncAttributeMaxDynamicSharedMemorySize, SMA_TOTAL);

    convert_all_kernel<<<3072, 256>>>(w_qkv, w_out, w1, w2, wqkv, wout, w1h, w2h);

    ln_kernel<<<SEQ, 256>>>(x, ln_g, ln_b, xn);
    gemm_mma<128, 0, false, true><<<dim3(1536 / 128, SEQ / 128), 256, SM128>>>(
        xn, wqkv, b_qkv, nullptr, nullptr, qkv, SEQ, 1536, 512);
    attn3_kernel<<<dim3(SEQ / TS, 8), 256, SMA_TOTAL>>>(qkv, attn);
    gemm_mma<64, 1, true, true><<<dim3(512 / 128, SEQ / 64), 256, SM64>>>(
        attn, wout, b_out, x, o_f, o_h, SEQ, 512, 512);
    gemm_mma<128, 2, false, true><<<dim3(2048 / 128, SEQ / 128), 256, SM128>>>(
        o_h, w1h, b1, nullptr, nullptr, f1, SEQ, 2048, 512);
    gemm_mma<64, 1, true, false><<<dim3(512 / 128, SEQ / 64), 256, SM64>>>(
        f1, w2h, b2, o_f, out, nullptr, SEQ, 512, 2048);
}